// round 2
// baseline (speedup 1.0000x reference)
#include <cuda_runtime.h>
#include <math.h>

#define TLEN   1024
#define BATCH  4
#define EMBED  1024
#define NH     16
#define HD     64
#define QSCALE 0.125f
#define MROWS  (TLEN * BATCH)   // 4096

// Scratch (static device allocations — allowed; no cudaMalloc anywhere)
__device__ float g_Q[BATCH * NH * TLEN * HD];                 // [b,h,t,d], pre-scaled
__device__ float g_K[BATCH * NH * TLEN * HD];
__device__ float g_V[BATCH * NH * TLEN * HD];
__device__ float g_P[(size_t)BATCH * NH * TLEN * TLEN];       // scores -> probs
__device__ float g_A[MROWS * EMBED];                          // attention context [t,b,e]

// ---------------------------------------------------------------------------
// K1: QKV projection. X[4096,1024] @ W[3072,1024]^T + bias, scattered into
// per-head Q/K/V layouts. 64x64 tile, BK=16, 4x4 per thread.
// ---------------------------------------------------------------------------
__global__ __launch_bounds__(256) void k_qkv(const float* __restrict__ X,
                                             const float* __restrict__ W,
                                             const float* __restrict__ bias) {
    __shared__ float As[64][17];
    __shared__ float Bs[64][17];
    const int tid = threadIdx.x;
    const int tx = tid & 15, ty = tid >> 4;
    const int m0 = blockIdx.y << 6;
    const int n0 = blockIdx.x << 6;
    const int lr = tid >> 2;
    const int lc = (tid & 3) << 2;
    const float* Arow = X + (size_t)(m0 + lr) * EMBED + lc;
    const float* Brow = W + (size_t)(n0 + lr) * EMBED + lc;
    float acc[4][4] = {};
    for (int k0 = 0; k0 < EMBED; k0 += 16) {
        float4 av = *(const float4*)(Arow + k0);
        float4 bv = *(const float4*)(Brow + k0);
        __syncthreads();
        As[lr][lc + 0] = av.x; As[lr][lc + 1] = av.y; As[lr][lc + 2] = av.z; As[lr][lc + 3] = av.w;
        Bs[lr][lc + 0] = bv.x; Bs[lr][lc + 1] = bv.y; Bs[lr][lc + 2] = bv.z; Bs[lr][lc + 3] = bv.w;
        __syncthreads();
        #pragma unroll
        for (int kk = 0; kk < 16; kk++) {
            float a[4], b[4];
            #pragma unroll
            for (int i = 0; i < 4; i++) a[i] = As[(ty << 2) + i][kk];
            #pragma unroll
            for (int j = 0; j < 4; j++) b[j] = Bs[(tx << 2) + j][kk];
            #pragma unroll
            for (int i = 0; i < 4; i++)
                #pragma unroll
                for (int j = 0; j < 4; j++)
                    acc[i][j] = fmaf(a[i], b[j], acc[i][j]);
        }
    }
    #pragma unroll
    for (int i = 0; i < 4; i++) {
        int m = m0 + (ty << 2) + i;
        int t = m >> 2, b = m & 3;   // row = t*BATCH + b
        #pragma unroll
        for (int j = 0; j < 4; j++) {
            int n = n0 + (tx << 2) + j;
            float v = acc[i][j] + bias[n];
            int c = n >> 10;          // 0=q, 1=k, 2=v
            int e = n & 1023;
            int h = e >> 6, d = e & 63;
            int idx = (((b << 4) + h) * TLEN + t) * HD + d;
            if (c == 0)      g_Q[idx] = v * QSCALE;
            else if (c == 1) g_K[idx] = v;
            else             g_V[idx] = v;
        }
    }
}

// ---------------------------------------------------------------------------
// K2a: scores = Q @ K^T per (b,h). 64x64 output tile, full K=64 in smem.
// Tiles entirely above the causal diagonal are skipped (softmax masks by
// position, never reading those values).
// ---------------------------------------------------------------------------
__global__ __launch_bounds__(256) void k_scores() {
    const int t0 = blockIdx.y << 6;
    const int s0 = blockIdx.x << 6;
    if (s0 > t0 + 63) return;   // structurally masked tile
    __shared__ float Qs[64][65];
    __shared__ float Ks[64][65];
    const int bh = blockIdx.z;
    const float* Qb = g_Q + (size_t)bh * TLEN * HD;
    const float* Kb = g_K + (size_t)bh * TLEN * HD;
    const int tid = threadIdx.x;
    const int lr = tid >> 2;
    const int lc = (tid & 3) << 4;
    #pragma unroll
    for (int u = 0; u < 16; u += 4) {
        float4 q = *(const float4*)(Qb + (t0 + lr) * HD + lc + u);
        float4 k = *(const float4*)(Kb + (s0 + lr) * HD + lc + u);
        Qs[lr][lc + u + 0] = q.x; Qs[lr][lc + u + 1] = q.y; Qs[lr][lc + u + 2] = q.z; Qs[lr][lc + u + 3] = q.w;
        Ks[lr][lc + u + 0] = k.x; Ks[lr][lc + u + 1] = k.y; Ks[lr][lc + u + 2] = k.z; Ks[lr][lc + u + 3] = k.w;
    }
    __syncthreads();
    const int tx = tid & 15, ty = tid >> 4;
    float acc[4][4] = {};
    #pragma unroll
    for (int kk = 0; kk < 64; kk++) {
        float a[4], b[4];
        #pragma unroll
        for (int i = 0; i < 4; i++) a[i] = Qs[(ty << 2) + i][kk];
        #pragma unroll
        for (int j = 0; j < 4; j++) b[j] = Ks[(tx << 2) + j][kk];
        #pragma unroll
        for (int i = 0; i < 4; i++)
            #pragma unroll
            for (int j = 0; j < 4; j++)
                acc[i][j] = fmaf(a[i], b[j], acc[i][j]);
    }
    float* out = g_P + ((size_t)bh * TLEN + t0 + (ty << 2)) * TLEN + s0 + (tx << 2);
    #pragma unroll
    for (int i = 0; i < 4; i++) {
        *(float4*)(out + (size_t)i * TLEN) =
            make_float4(acc[i][0], acc[i][1], acc[i][2], acc[i][3]);
    }
}

// ---------------------------------------------------------------------------
// K2b: row softmax in place, applying causal + key-padding masks positionally.
// pad mask is int32 (numpy bool widened by the harness).
// Masked entries -> exactly 0 (matches reference: exp(-1e9 - m) underflows).
// ---------------------------------------------------------------------------
__global__ __launch_bounds__(256) void k_softmax(const int* __restrict__ pad) {
    const int t  = blockIdx.x;
    const int bh = blockIdx.y;
    const int b  = bh >> 4;
    float* row = g_P + ((size_t)bh * TLEN + t) * TLEN;
    const int tid = threadIdx.x;
    float v[4];
    bool ok[4];
    #pragma unroll
    for (int k = 0; k < 4; k++) {
        int s = tid + (k << 8);
        float sc = row[s];
        ok[k] = (s <= t) && (pad[b * TLEN + s] == 0);
        v[k] = ok[k] ? sc : -1e30f;
    }
    __shared__ float redm[8];
    __shared__ float reds[8];
    float m = fmaxf(fmaxf(v[0], v[1]), fmaxf(v[2], v[3]));
    #pragma unroll
    for (int o = 16; o; o >>= 1) m = fmaxf(m, __shfl_xor_sync(0xffffffffu, m, o));
    if ((tid & 31) == 0) redm[tid >> 5] = m;
    __syncthreads();
    m = fmaxf(fmaxf(fmaxf(redm[0], redm[1]), fmaxf(redm[2], redm[3])),
              fmaxf(fmaxf(redm[4], redm[5]), fmaxf(redm[6], redm[7])));
    float e[4], sum = 0.f;
    #pragma unroll
    for (int k = 0; k < 4; k++) {
        e[k] = ok[k] ? __expf(v[k] - m) : 0.f;
        sum += e[k];
    }
    #pragma unroll
    for (int o = 16; o; o >>= 1) sum += __shfl_xor_sync(0xffffffffu, sum, o);
    if ((tid & 31) == 0) reds[tid >> 5] = sum;
    __syncthreads();
    sum = reds[0] + reds[1] + reds[2] + reds[3] + reds[4] + reds[5] + reds[6] + reds[7];
    float inv = 1.f / sum;
    #pragma unroll
    for (int k = 0; k < 4; k++)
        row[tid + (k << 8)] = e[k] * inv;
}

// ---------------------------------------------------------------------------
// K2c: avg_weights[b,t,s] = mean over heads of probs
// ---------------------------------------------------------------------------
__global__ __launch_bounds__(256) void k_avg(float* __restrict__ outAvg) {
    const int idx = blockIdx.x * 256 + threadIdx.x;   // < B*T*T = 4194304
    const int s = idx & 1023;
    const int t = (idx >> 10) & 1023;
    const int b = idx >> 20;
    const float* base = g_P + ((size_t)(b << 4) * TLEN + t) * TLEN + s;
    float sum = 0.f;
    #pragma unroll
    for (int h = 0; h < 16; h++)
        sum += base[(size_t)h * TLEN * TLEN];
    outAvg[idx] = sum * 0.0625f;
}

// ---------------------------------------------------------------------------
// K2d: context = P @ V per (b,h). BM=64, BN=64(=HD), BK=16. K-loop truncated
// at the causal diagonal (probs are exactly 0 beyond it).
// ---------------------------------------------------------------------------
__global__ __launch_bounds__(256) void k_pv() {
    __shared__ float Ps[64][17];
    __shared__ float Vs[16][65];
    const int t0 = blockIdx.x << 6;
    const int bh = blockIdx.y;
    const float* Pb = g_P + (size_t)bh * TLEN * TLEN;
    const float* Vb = g_V + (size_t)bh * TLEN * HD;
    const int tid = threadIdx.x;
    const int tx = tid & 15, ty = tid >> 4;
    const int lrP = tid >> 2, lcP = (tid & 3) << 2;
    const int smax = t0 + 64;
    float acc[4][4] = {};
    for (int s0 = 0; s0 < smax; s0 += 16) {
        float4 p  = *(const float4*)(Pb + (size_t)(t0 + lrP) * TLEN + s0 + lcP);
        float4 vv = *(const float4*)(Vb + (s0 + ty) * HD + (tx << 2));
        __syncthreads();
        Ps[lrP][lcP + 0] = p.x; Ps[lrP][lcP + 1] = p.y; Ps[lrP][lcP + 2] = p.z; Ps[lrP][lcP + 3] = p.w;
        Vs[ty][(tx << 2) + 0] = vv.x; Vs[ty][(tx << 2) + 1] = vv.y;
        Vs[ty][(tx << 2) + 2] = vv.z; Vs[ty][(tx << 2) + 3] = vv.w;
        __syncthreads();
        #pragma unroll
        for (int kk = 0; kk < 16; kk++) {
            float a[4], b[4];
            #pragma unroll
            for (int i = 0; i < 4; i++) a[i] = Ps[(ty << 2) + i][kk];
            #pragma unroll
            for (int j = 0; j < 4; j++) b[j] = Vs[kk][(tx << 2) + j];
            #pragma unroll
            for (int i = 0; i < 4; i++)
                #pragma unroll
                for (int j = 0; j < 4; j++)
                    acc[i][j] = fmaf(a[i], b[j], acc[i][j]);
        }
    }
    const int b_ = bh >> 4, h = bh & 15;
    #pragma unroll
    for (int i = 0; i < 4; i++) {
        int t = t0 + (ty << 2) + i;
        float* o = g_A + ((size_t)t * BATCH + b_) * EMBED + (h << 6) + (tx << 2);
        *(float4*)o = make_float4(acc[i][0], acc[i][1], acc[i][2], acc[i][3]);
    }
}

// ---------------------------------------------------------------------------
// K3: output projection. g_A[4096,1024] @ out_w[1024,1024]^T + out_b -> d_out
// ---------------------------------------------------------------------------
__global__ __launch_bounds__(256) void k_oproj(const float* __restrict__ W,
                                               const float* __restrict__ bias,
                                               float* __restrict__ out) {
    __shared__ float As[64][17];
    __shared__ float Bs[64][17];
    const int tid = threadIdx.x;
    const int tx = tid & 15, ty = tid >> 4;
    const int m0 = blockIdx.y << 6;
    const int n0 = blockIdx.x << 6;
    const int lr = tid >> 2;
    const int lc = (tid & 3) << 2;
    const float* Arow = g_A + (size_t)(m0 + lr) * EMBED + lc;
    const float* Brow = W + (size_t)(n0 + lr) * EMBED + lc;
    float acc[4][4] = {};
    for (int k0 = 0; k0 < EMBED; k0 += 16) {
        float4 av = *(const float4*)(Arow + k0);
        float4 bv = *(const float4*)(Brow + k0);
        __syncthreads();
        As[lr][lc + 0] = av.x; As[lr][lc + 1] = av.y; As[lr][lc + 2] = av.z; As[lr][lc + 3] = av.w;
        Bs[lr][lc + 0] = bv.x; Bs[lr][lc + 1] = bv.y; Bs[lr][lc + 2] = bv.z; Bs[lr][lc + 3] = bv.w;
        __syncthreads();
        #pragma unroll
        for (int kk = 0; kk < 16; kk++) {
            float a[4], b[4];
            #pragma unroll
            for (int i = 0; i < 4; i++) a[i] = As[(ty << 2) + i][kk];
            #pragma unroll
            for (int j = 0; j < 4; j++) b[j] = Bs[(tx << 2) + j][kk];
            #pragma unroll
            for (int i = 0; i < 4; i++)
                #pragma unroll
                for (int j = 0; j < 4; j++)
                    acc[i][j] = fmaf(a[i], b[j], acc[i][j]);
        }
    }
    #pragma unroll
    for (int i = 0; i < 4; i++) {
        int m = m0 + (ty << 2) + i;
        float* o = out + (size_t)m * EMBED + n0 + (tx << 2);
        *(float4*)o = make_float4(acc[i][0] + bias[n0 + (tx << 2) + 0],
                                  acc[i][1] + bias[n0 + (tx << 2) + 1],
                                  acc[i][2] + bias[n0 + (tx << 2) + 2],
                                  acc[i][3] + bias[n0 + (tx << 2) + 3]);
    }
}

// ---------------------------------------------------------------------------
extern "C" void kernel_launch(void* const* d_in, const int* in_sizes, int n_in,
                              void* d_out, int out_size) {
    const float* query = (const float*)d_in[0];
    const int*   mask  = (const int*)d_in[1];   // numpy bool widened to int32
    const float* w_in  = (const float*)d_in[2];
    const float* b_in  = (const float*)d_in[3];
    const float* w_out = (const float*)d_in[4];
    const float* b_out = (const float*)d_in[5];

    float* outAttn = (float*)d_out;                                   // [T,B,E]
    float* outAvg  = (float*)d_out + (size_t)MROWS * EMBED;           // [B,T,S]

    k_qkv    <<<dim3(48, 64), 256>>>(query, w_in, b_in);
    k_scores <<<dim3(16, 16, 64), 256>>>();
    k_softmax<<<dim3(1024, 64), 256>>>(mask);
    k_avg    <<<16384, 256>>>(outAvg);
    k_pv     <<<dim3(16, 64), 256>>>();
    k_oproj  <<<dim3(16, 64), 256>>>(w_out, b_out, outAttn);
}

// round 4
// speedup vs baseline: 1.9550x; 1.9550x over previous
#include <cuda_runtime.h>
#include <math.h>
#include <stdint.h>

#define TLEN   1024
#define BATCH  4
#define EMBED  1024
#define NH     16
#define HD     64
#define QSCALE 0.125f
#define MROWS  (TLEN * BATCH)   // 4096

// Scratch (static device globals — no cudaMalloc anywhere)
__device__ float g_Q[BATCH * NH * TLEN * HD];                 // [b,h,t,d], pre-scaled
__device__ float g_K[BATCH * NH * TLEN * HD];
__device__ float g_V[BATCH * NH * TLEN * HD];
__device__ float g_P[(size_t)BATCH * NH * TLEN * TLEN];       // scores -> probs
__device__ float g_A[MROWS * EMBED];                          // attention context [t,b,e]

__device__ __forceinline__ uint32_t f2tf(float f) {
    uint32_t u;
    asm("cvt.rna.tf32.f32 %0, %1;" : "=r"(u) : "f"(f));
    return u;
}

// ---------------------------------------------------------------------------
// TF32 tensor-core GEMM: C[M,N] = A[M,K] @ B[N,K]^T + bias
// CTA tile 128x128, BK=32, 256 threads = 8 warps (2m x 4n), warp tile 64x32,
// mma.sync.m16n8k8. EPI=0: A from arg (query), scatter into g_Q/g_K/g_V.
// EPI=1: A = g_A (device symbol — must be resolved in DEVICE code), C += bias.
// ---------------------------------------------------------------------------
template <int EPI>
__global__ __launch_bounds__(256) void k_gemm_tf32(const float* __restrict__ Ain,
                                                   const float* __restrict__ B,
                                                   const float* __restrict__ bias,
                                                   float* __restrict__ C,
                                                   int K) {
    const float* A = (EPI == 0) ? Ain : (const float*)g_A;   // device-side symbol
    __shared__ uint32_t As[128][36];
    __shared__ uint32_t Bs[128][36];
    const int tid  = threadIdx.x;
    const int lane = tid & 31;
    const int wid  = tid >> 5;
    const int wm   = (wid & 1) << 6;    // warp m offset: 0/64
    const int wn   = (wid >> 1) << 5;   // warp n offset: 0/32/64/96
    const int m0   = blockIdx.y << 7;
    const int n0   = blockIdx.x << 7;

    const int ldr = tid >> 3;           // 0..31 (row within 32-row chunk)
    const int ldc = (tid & 7) << 2;     // 0..28 (k col, step 4)

    const int g4 = lane >> 2;           // group id 0..7
    const int g1 = lane & 3;            // thread-in-group 0..3

    float acc[4][4][4] = {};

    for (int k0 = 0; k0 < K; k0 += 32) {
        float4 av[4], bv[4];
        #pragma unroll
        for (int r = 0; r < 4; r++) {
            av[r] = *(const float4*)(A + (size_t)(m0 + (r << 5) + ldr) * K + k0 + ldc);
            bv[r] = *(const float4*)(B + (size_t)(n0 + (r << 5) + ldr) * K + k0 + ldc);
        }
        __syncthreads();
        #pragma unroll
        for (int r = 0; r < 4; r++) {
            uint32_t* pa = &As[(r << 5) + ldr][ldc];
            uint32_t* pb = &Bs[(r << 5) + ldr][ldc];
            pa[0] = f2tf(av[r].x); pa[1] = f2tf(av[r].y); pa[2] = f2tf(av[r].z); pa[3] = f2tf(av[r].w);
            pb[0] = f2tf(bv[r].x); pb[1] = f2tf(bv[r].y); pb[2] = f2tf(bv[r].z); pb[3] = f2tf(bv[r].w);
        }
        __syncthreads();
        #pragma unroll
        for (int kk = 0; kk < 32; kk += 8) {
            uint32_t a[4][4], b[4][2];
            #pragma unroll
            for (int im = 0; im < 4; im++) {
                int mr = wm + (im << 4) + g4;
                a[im][0] = As[mr    ][kk + g1    ];
                a[im][1] = As[mr + 8][kk + g1    ];
                a[im][2] = As[mr    ][kk + g1 + 4];
                a[im][3] = As[mr + 8][kk + g1 + 4];
            }
            #pragma unroll
            for (int jn = 0; jn < 4; jn++) {
                int nr = wn + (jn << 3) + g4;
                b[jn][0] = Bs[nr][kk + g1    ];
                b[jn][1] = Bs[nr][kk + g1 + 4];
            }
            #pragma unroll
            for (int im = 0; im < 4; im++)
                #pragma unroll
                for (int jn = 0; jn < 4; jn++)
                    asm volatile(
                        "mma.sync.aligned.m16n8k8.row.col.f32.tf32.tf32.f32 "
                        "{%0,%1,%2,%3}, {%4,%5,%6,%7}, {%8,%9}, {%0,%1,%2,%3};"
                        : "+f"(acc[im][jn][0]), "+f"(acc[im][jn][1]),
                          "+f"(acc[im][jn][2]), "+f"(acc[im][jn][3])
                        : "r"(a[im][0]), "r"(a[im][1]), "r"(a[im][2]), "r"(a[im][3]),
                          "r"(b[jn][0]), "r"(b[jn][1]));
        }
    }

    #pragma unroll
    for (int im = 0; im < 4; im++) {
        #pragma unroll
        for (int jn = 0; jn < 4; jn++) {
            #pragma unroll
            for (int e = 0; e < 4; e++) {
                int m = m0 + wm + (im << 4) + g4 + ((e >> 1) << 3);
                int n = n0 + wn + (jn << 3) + (g1 << 1) + (e & 1);
                float v = acc[im][jn][e] + bias[n];
                if (EPI == 0) {
                    int t = m >> 2, bb = m & 3;
                    int c = n >> 10;
                    int ee = n & 1023;
                    int h = ee >> 6, d = ee & 63;
                    int idx = (((bb << 4) + h) * TLEN + t) * HD + d;
                    if (c == 0)      g_Q[idx] = v * QSCALE;
                    else if (c == 1) g_K[idx] = v;
                    else             g_V[idx] = v;
                } else {
                    C[(size_t)m * EMBED + n] = v;
                }
            }
        }
    }
}

// ---------------------------------------------------------------------------
// K2a: scores = Q @ K^T per (b,h). Tiles above the causal diagonal skipped.
// ---------------------------------------------------------------------------
__global__ __launch_bounds__(256) void k_scores() {
    const int t0 = blockIdx.y << 6;
    const int s0 = blockIdx.x << 6;
    if (s0 > t0 + 63) return;   // structurally masked tile
    __shared__ float Qs[64][65];
    __shared__ float Ks[64][65];
    const int bh = blockIdx.z;
    const float* Qb = g_Q + (size_t)bh * TLEN * HD;
    const float* Kb = g_K + (size_t)bh * TLEN * HD;
    const int tid = threadIdx.x;
    const int lr = tid >> 2;
    const int lc = (tid & 3) << 4;
    #pragma unroll
    for (int u = 0; u < 16; u += 4) {
        float4 q = *(const float4*)(Qb + (t0 + lr) * HD + lc + u);
        float4 k = *(const float4*)(Kb + (s0 + lr) * HD + lc + u);
        Qs[lr][lc + u + 0] = q.x; Qs[lr][lc + u + 1] = q.y; Qs[lr][lc + u + 2] = q.z; Qs[lr][lc + u + 3] = q.w;
        Ks[lr][lc + u + 0] = k.x; Ks[lr][lc + u + 1] = k.y; Ks[lr][lc + u + 2] = k.z; Ks[lr][lc + u + 3] = k.w;
    }
    __syncthreads();
    const int tx = tid & 15, ty = tid >> 4;
    float acc[4][4] = {};
    #pragma unroll
    for (int kk = 0; kk < 64; kk++) {
        float a[4], b[4];
        #pragma unroll
        for (int i = 0; i < 4; i++) a[i] = Qs[(ty << 2) + i][kk];
        #pragma unroll
        for (int j = 0; j < 4; j++) b[j] = Ks[(tx << 2) + j][kk];
        #pragma unroll
        for (int i = 0; i < 4; i++)
            #pragma unroll
            for (int j = 0; j < 4; j++)
                acc[i][j] = fmaf(a[i], b[j], acc[i][j]);
    }
    float* out = g_P + ((size_t)bh * TLEN + t0 + (ty << 2)) * TLEN + s0 + (tx << 2);
    #pragma unroll
    for (int i = 0; i < 4; i++) {
        *(float4*)(out + (size_t)i * TLEN) =
            make_float4(acc[i][0], acc[i][1], acc[i][2], acc[i][3]);
    }
}

// ---------------------------------------------------------------------------
// K2b: row softmax in place; causal + padding (int32) masks applied
// positionally; masked entries produce exactly 0.
// ---------------------------------------------------------------------------
__global__ __launch_bounds__(256) void k_softmax(const int* __restrict__ pad) {
    const int t  = blockIdx.x;
    const int bh = blockIdx.y;
    const int b  = bh >> 4;
    float* row = g_P + ((size_t)bh * TLEN + t) * TLEN;
    const int tid = threadIdx.x;
    float v[4];
    bool ok[4];
    #pragma unroll
    for (int k = 0; k < 4; k++) {
        int s = tid + (k << 8);
        float sc = row[s];
        ok[k] = (s <= t) && (pad[b * TLEN + s] == 0);
        v[k] = ok[k] ? sc : -1e30f;
    }
    __shared__ float redm[8];
    __shared__ float reds[8];
    float m = fmaxf(fmaxf(v[0], v[1]), fmaxf(v[2], v[3]));
    #pragma unroll
    for (int o = 16; o; o >>= 1) m = fmaxf(m, __shfl_xor_sync(0xffffffffu, m, o));
    if ((tid & 31) == 0) redm[tid >> 5] = m;
    __syncthreads();
    m = fmaxf(fmaxf(fmaxf(redm[0], redm[1]), fmaxf(redm[2], redm[3])),
              fmaxf(fmaxf(redm[4], redm[5]), fmaxf(redm[6], redm[7])));
    float e[4], sum = 0.f;
    #pragma unroll
    for (int k = 0; k < 4; k++) {
        e[k] = ok[k] ? __expf(v[k] - m) : 0.f;
        sum += e[k];
    }
    #pragma unroll
    for (int o = 16; o; o >>= 1) sum += __shfl_xor_sync(0xffffffffu, sum, o);
    if ((tid & 31) == 0) reds[tid >> 5] = sum;
    __syncthreads();
    sum = reds[0] + reds[1] + reds[2] + reds[3] + reds[4] + reds[5] + reds[6] + reds[7];
    float inv = 1.f / sum;
    #pragma unroll
    for (int k = 0; k < 4; k++)
        row[tid + (k << 8)] = e[k] * inv;
}

// ---------------------------------------------------------------------------
// K2c: avg_weights[b,t,s] = mean over heads of probs (DRAM-bound, 83% SOL)
// ---------------------------------------------------------------------------
__global__ __launch_bounds__(256) void k_avg(float* __restrict__ outAvg) {
    const int idx = blockIdx.x * 256 + threadIdx.x;   // < B*T*T = 4194304
    const int s = idx & 1023;
    const int t = (idx >> 10) & 1023;
    const int b = idx >> 20;
    const float* base = g_P + ((size_t)(b << 4) * TLEN + t) * TLEN + s;
    float sum = 0.f;
    #pragma unroll
    for (int h = 0; h < 16; h++)
        sum += base[(size_t)h * TLEN * TLEN];
    outAvg[idx] = sum * 0.0625f;
}

// ---------------------------------------------------------------------------
// K2d: context = P @ V per (b,h); K-loop truncated at causal diagonal.
// ---------------------------------------------------------------------------
__global__ __launch_bounds__(256) void k_pv() {
    __shared__ float Ps[64][17];
    __shared__ float Vs[16][65];
    const int t0 = blockIdx.x << 6;
    const int bh = blockIdx.y;
    const float* Pb = g_P + (size_t)bh * TLEN * TLEN;
    const float* Vb = g_V + (size_t)bh * TLEN * HD;
    const int tid = threadIdx.x;
    const int tx = tid & 15, ty = tid >> 4;
    const int lrP = tid >> 2, lcP = (tid & 3) << 2;
    const int smax = t0 + 64;
    float acc[4][4] = {};
    for (int s0 = 0; s0 < smax; s0 += 16) {
        float4 p  = *(const float4*)(Pb + (size_t)(t0 + lrP) * TLEN + s0 + lcP);
        float4 vv = *(const float4*)(Vb + (s0 + ty) * HD + (tx << 2));
        __syncthreads();
        Ps[lrP][lcP + 0] = p.x; Ps[lrP][lcP + 1] = p.y; Ps[lrP][lcP + 2] = p.z; Ps[lrP][lcP + 3] = p.w;
        Vs[ty][(tx << 2) + 0] = vv.x; Vs[ty][(tx << 2) + 1] = vv.y;
        Vs[ty][(tx << 2) + 2] = vv.z; Vs[ty][(tx << 2) + 3] = vv.w;
        __syncthreads();
        #pragma unroll
        for (int kk = 0; kk < 16; kk++) {
            float a[4], b[4];
            #pragma unroll
            for (int i = 0; i < 4; i++) a[i] = Ps[(ty << 2) + i][kk];
            #pragma unroll
            for (int j = 0; j < 4; j++) b[j] = Vs[kk][(tx << 2) + j];
            #pragma unroll
            for (int i = 0; i < 4; i++)
                #pragma unroll
                for (int j = 0; j < 4; j++)
                    acc[i][j] = fmaf(a[i], b[j], acc[i][j]);
        }
    }
    const int b_ = bh >> 4, h = bh & 15;
    #pragma unroll
    for (int i = 0; i < 4; i++) {
        int t = t0 + (ty << 2) + i;
        float* o = g_A + ((size_t)t * BATCH + b_) * EMBED + (h << 6) + (tx << 2);
        *(float4*)o = make_float4(acc[i][0], acc[i][1], acc[i][2], acc[i][3]);
    }
}

// ---------------------------------------------------------------------------
extern "C" void kernel_launch(void* const* d_in, const int* in_sizes, int n_in,
                              void* d_out, int out_size) {
    const float* query = (const float*)d_in[0];
    const int*   mask  = (const int*)d_in[1];   // numpy bool widened to int32
    const float* w_in  = (const float*)d_in[2];
    const float* b_in  = (const float*)d_in[3];
    const float* w_out = (const float*)d_in[4];
    const float* b_out = (const float*)d_in[5];

    float* outAttn = (float*)d_out;                                   // [T,B,E]
    float* outAvg  = (float*)d_out + (size_t)MROWS * EMBED;           // [B,T,S]

    k_gemm_tf32<0><<<dim3(24, 32), 256>>>(query, w_in, b_in, nullptr, EMBED);
    k_scores <<<dim3(16, 16, 64), 256>>>();
    k_softmax<<<dim3(1024, 64), 256>>>(mask);
    k_avg    <<<16384, 256>>>(outAvg);
    k_pv     <<<dim3(16, 64), 256>>>();
    k_gemm_tf32<1><<<dim3(8, 32), 256>>>(nullptr, w_out, b_out, outAttn, EMBED);
}

// round 5
// speedup vs baseline: 2.6785x; 1.3701x over previous
#include <cuda_runtime.h>
#include <math.h>
#include <stdint.h>

#define TLEN   1024
#define BATCH  4
#define EMBED  1024
#define NH     16
#define HD     64
#define QSCALE 0.125f
#define MROWS  (TLEN * BATCH)   // 4096

// Scratch (static device globals — no cudaMalloc anywhere)
__device__ float g_Q[BATCH * NH * TLEN * HD];                 // [b,h,t,d], pre-scaled
__device__ float g_K[BATCH * NH * TLEN * HD];
__device__ float g_V[BATCH * NH * TLEN * HD];
__device__ float g_P[(size_t)BATCH * NH * TLEN * TLEN];       // scores -> probs
__device__ float g_A[MROWS * EMBED];                          // attention context [t,b,e]

__device__ __forceinline__ uint32_t f2tf(float f) {
    uint32_t u;
    asm("cvt.rna.tf32.f32 %0, %1;" : "=r"(u) : "f"(f));
    return u;
}

__device__ __forceinline__ void mma_tf32(float* d, const uint32_t* a, const uint32_t* b) {
    asm volatile(
        "mma.sync.aligned.m16n8k8.row.col.f32.tf32.tf32.f32 "
        "{%0,%1,%2,%3}, {%4,%5,%6,%7}, {%8,%9}, {%0,%1,%2,%3};"
        : "+f"(d[0]), "+f"(d[1]), "+f"(d[2]), "+f"(d[3])
        : "r"(a[0]), "r"(a[1]), "r"(a[2]), "r"(a[3]), "r"(b[0]), "r"(b[1]));
}

// ---------------------------------------------------------------------------
// TF32 tensor-core GEMM: C[M,N] = A[M,K] @ B[N,K]^T + bias
// CTA 128x128, BK=32, 8 warps (2m x 4n), warp tile 64x32, mma m16n8k8.
// EPI=0: A=query, scatter into g_Q/g_K/g_V. EPI=1: A=g_A (device symbol), C.
// ---------------------------------------------------------------------------
template <int EPI>
__global__ __launch_bounds__(256) void k_gemm_tf32(const float* __restrict__ Ain,
                                                   const float* __restrict__ B,
                                                   const float* __restrict__ bias,
                                                   float* __restrict__ C,
                                                   int K) {
    const float* A = (EPI == 0) ? Ain : (const float*)g_A;
    __shared__ uint32_t As[128][36];
    __shared__ uint32_t Bs[128][36];
    const int tid  = threadIdx.x;
    const int lane = tid & 31;
    const int wid  = tid >> 5;
    const int wm   = (wid & 1) << 6;
    const int wn   = (wid >> 1) << 5;
    const int m0   = blockIdx.y << 7;
    const int n0   = blockIdx.x << 7;
    const int ldr = tid >> 3;
    const int ldc = (tid & 7) << 2;
    const int g4 = lane >> 2;
    const int g1 = lane & 3;

    float acc[4][4][4] = {};

    for (int k0 = 0; k0 < K; k0 += 32) {
        float4 av[4], bv[4];
        #pragma unroll
        for (int r = 0; r < 4; r++) {
            av[r] = *(const float4*)(A + (size_t)(m0 + (r << 5) + ldr) * K + k0 + ldc);
            bv[r] = *(const float4*)(B + (size_t)(n0 + (r << 5) + ldr) * K + k0 + ldc);
        }
        __syncthreads();
        #pragma unroll
        for (int r = 0; r < 4; r++) {
            uint32_t* pa = &As[(r << 5) + ldr][ldc];
            uint32_t* pb = &Bs[(r << 5) + ldr][ldc];
            pa[0] = f2tf(av[r].x); pa[1] = f2tf(av[r].y); pa[2] = f2tf(av[r].z); pa[3] = f2tf(av[r].w);
            pb[0] = f2tf(bv[r].x); pb[1] = f2tf(bv[r].y); pb[2] = f2tf(bv[r].z); pb[3] = f2tf(bv[r].w);
        }
        __syncthreads();
        #pragma unroll
        for (int kk = 0; kk < 32; kk += 8) {
            uint32_t a[4][4], b[4][2];
            #pragma unroll
            for (int im = 0; im < 4; im++) {
                int mr = wm + (im << 4) + g4;
                a[im][0] = As[mr    ][kk + g1    ];
                a[im][1] = As[mr + 8][kk + g1    ];
                a[im][2] = As[mr    ][kk + g1 + 4];
                a[im][3] = As[mr + 8][kk + g1 + 4];
            }
            #pragma unroll
            for (int jn = 0; jn < 4; jn++) {
                int nr = wn + (jn << 3) + g4;
                b[jn][0] = Bs[nr][kk + g1    ];
                b[jn][1] = Bs[nr][kk + g1 + 4];
            }
            #pragma unroll
            for (int im = 0; im < 4; im++)
                #pragma unroll
                for (int jn = 0; jn < 4; jn++)
                    mma_tf32(acc[im][jn], a[im], b[jn]);
        }
    }

    #pragma unroll
    for (int im = 0; im < 4; im++)
        #pragma unroll
        for (int jn = 0; jn < 4; jn++)
            #pragma unroll
            for (int e = 0; e < 4; e++) {
                int m = m0 + wm + (im << 4) + g4 + ((e >> 1) << 3);
                int n = n0 + wn + (jn << 3) + (g1 << 1) + (e & 1);
                float v = acc[im][jn][e] + bias[n];
                if (EPI == 0) {
                    int t = m >> 2, bb = m & 3;
                    int c = n >> 10;
                    int ee = n & 1023;
                    int h = ee >> 6, d = ee & 63;
                    int idx = (((bb << 4) + h) * TLEN + t) * HD + d;
                    if (c == 0)      g_Q[idx] = v * QSCALE;
                    else if (c == 1) g_K[idx] = v;
                    else             g_V[idx] = v;
                } else {
                    C[(size_t)m * EMBED + n] = v;
                }
            }
}

// ---------------------------------------------------------------------------
// K2a: scores = Q @ K^T per (b,h), TF32 MMA. 128x128 tiles, K=64 (2 x BK=32).
// Tiles entirely above the causal diagonal are skipped.
// ---------------------------------------------------------------------------
__global__ __launch_bounds__(256) void k_scores_mma() {
    const int t0 = blockIdx.y << 7;
    const int s0 = blockIdx.x << 7;
    if (s0 > t0 + 127) return;        // structurally masked tile
    __shared__ uint32_t Qs[128][36];
    __shared__ uint32_t Ks[128][36];
    const int bh = blockIdx.z;
    const float* Qb = g_Q + (size_t)bh * TLEN * HD;
    const float* Kb = g_K + (size_t)bh * TLEN * HD;
    const int tid  = threadIdx.x;
    const int lane = tid & 31;
    const int wid  = tid >> 5;
    const int wm   = (wid & 1) << 6;
    const int wn   = (wid >> 1) << 5;
    const int ldr = tid >> 3;
    const int ldc = (tid & 7) << 2;
    const int g4 = lane >> 2;
    const int g1 = lane & 3;

    float acc[4][4][4] = {};

    #pragma unroll
    for (int k0 = 0; k0 < 64; k0 += 32) {
        float4 qv[4], kv[4];
        #pragma unroll
        for (int r = 0; r < 4; r++) {
            qv[r] = *(const float4*)(Qb + (size_t)(t0 + (r << 5) + ldr) * HD + k0 + ldc);
            kv[r] = *(const float4*)(Kb + (size_t)(s0 + (r << 5) + ldr) * HD + k0 + ldc);
        }
        __syncthreads();
        #pragma unroll
        for (int r = 0; r < 4; r++) {
            uint32_t* pq = &Qs[(r << 5) + ldr][ldc];
            uint32_t* pk = &Ks[(r << 5) + ldr][ldc];
            pq[0] = f2tf(qv[r].x); pq[1] = f2tf(qv[r].y); pq[2] = f2tf(qv[r].z); pq[3] = f2tf(qv[r].w);
            pk[0] = f2tf(kv[r].x); pk[1] = f2tf(kv[r].y); pk[2] = f2tf(kv[r].z); pk[3] = f2tf(kv[r].w);
        }
        __syncthreads();
        #pragma unroll
        for (int kk = 0; kk < 32; kk += 8) {
            uint32_t a[4][4], b[4][2];
            #pragma unroll
            for (int im = 0; im < 4; im++) {
                int mr = wm + (im << 4) + g4;
                a[im][0] = Qs[mr    ][kk + g1    ];
                a[im][1] = Qs[mr + 8][kk + g1    ];
                a[im][2] = Qs[mr    ][kk + g1 + 4];
                a[im][3] = Qs[mr + 8][kk + g1 + 4];
            }
            #pragma unroll
            for (int jn = 0; jn < 4; jn++) {
                int nr = wn + (jn << 3) + g4;
                b[jn][0] = Ks[nr][kk + g1    ];
                b[jn][1] = Ks[nr][kk + g1 + 4];
            }
            #pragma unroll
            for (int im = 0; im < 4; im++)
                #pragma unroll
                for (int jn = 0; jn < 4; jn++)
                    mma_tf32(acc[im][jn], a[im], b[jn]);
        }
    }

    float* out = g_P + (size_t)bh * TLEN * TLEN;
    #pragma unroll
    for (int im = 0; im < 4; im++)
        #pragma unroll
        for (int jn = 0; jn < 4; jn++)
            #pragma unroll
            for (int ep = 0; ep < 2; ep++) {
                int t = t0 + wm + (im << 4) + g4 + (ep << 3);
                int s = s0 + wn + (jn << 3) + (g1 << 1);
                float2 v2 = make_float2(acc[im][jn][ep << 1], acc[im][jn][(ep << 1) + 1]);
                *(float2*)(out + (size_t)t * TLEN + s) = v2;
            }
}

// ---------------------------------------------------------------------------
// K2b: row softmax in place; causal + padding (int32) masks applied
// positionally; masked entries produce exactly 0.
// ---------------------------------------------------------------------------
__global__ __launch_bounds__(256) void k_softmax(const int* __restrict__ pad) {
    const int t  = blockIdx.x;
    const int bh = blockIdx.y;
    const int b  = bh >> 4;
    float* row = g_P + ((size_t)bh * TLEN + t) * TLEN;
    const int tid = threadIdx.x;
    float v[4];
    bool ok[4];
    #pragma unroll
    for (int k = 0; k < 4; k++) {
        int s = tid + (k << 8);
        float sc = row[s];
        ok[k] = (s <= t) && (pad[b * TLEN + s] == 0);
        v[k] = ok[k] ? sc : -1e30f;
    }
    __shared__ float redm[8];
    __shared__ float reds[8];
    float m = fmaxf(fmaxf(v[0], v[1]), fmaxf(v[2], v[3]));
    #pragma unroll
    for (int o = 16; o; o >>= 1) m = fmaxf(m, __shfl_xor_sync(0xffffffffu, m, o));
    if ((tid & 31) == 0) redm[tid >> 5] = m;
    __syncthreads();
    m = fmaxf(fmaxf(fmaxf(redm[0], redm[1]), fmaxf(redm[2], redm[3])),
              fmaxf(fmaxf(redm[4], redm[5]), fmaxf(redm[6], redm[7])));
    float e[4], sum = 0.f;
    #pragma unroll
    for (int k = 0; k < 4; k++) {
        e[k] = ok[k] ? __expf(v[k] - m) : 0.f;
        sum += e[k];
    }
    #pragma unroll
    for (int o = 16; o; o >>= 1) sum += __shfl_xor_sync(0xffffffffu, sum, o);
    if ((tid & 31) == 0) reds[tid >> 5] = sum;
    __syncthreads();
    sum = reds[0] + reds[1] + reds[2] + reds[3] + reds[4] + reds[5] + reds[6] + reds[7];
    float inv = 1.f / sum;
    #pragma unroll
    for (int k = 0; k < 4; k++)
        row[tid + (k << 8)] = e[k] * inv;
}

// ---------------------------------------------------------------------------
// K2c: avg_weights[b,t,s] = mean over heads (DRAM-bound, ~81% SOL — done)
// ---------------------------------------------------------------------------
__global__ __launch_bounds__(256) void k_avg(float* __restrict__ outAvg) {
    const int idx = blockIdx.x * 256 + threadIdx.x;
    const int s = idx & 1023;
    const int t = (idx >> 10) & 1023;
    const int b = idx >> 20;
    const float* base = g_P + ((size_t)(b << 4) * TLEN + t) * TLEN + s;
    float sum = 0.f;
    #pragma unroll
    for (int h = 0; h < 16; h++)
        sum += base[(size_t)h * TLEN * TLEN];
    outAvg[idx] = sum * 0.0625f;
}

// ---------------------------------------------------------------------------
// K2d: context = P @ V per (b,h), TF32 MMA. CTA = 128 t-rows x 64 d-cols,
// K-loop (s) truncated at causal diagonal (P holds exact zeros above it).
// 8 warps (4m x 2n), warp tile 32x32. V transposed into smem at load.
// ---------------------------------------------------------------------------
__global__ __launch_bounds__(256) void k_pv_mma() {
    __shared__ uint32_t Ps[128][36];
    __shared__ uint32_t Vs[64][36];
    const int t0 = blockIdx.x << 7;
    const int bh = blockIdx.y;
    const float* Pb = g_P + (size_t)bh * TLEN * TLEN;
    const float* Vb = g_V + (size_t)bh * TLEN * HD;
    const int tid  = threadIdx.x;
    const int lane = tid & 31;
    const int wid  = tid >> 5;
    const int wm   = (wid & 3) << 5;   // 0/32/64/96
    const int wn   = (wid >> 2) << 5;  // 0/32
    const int ldr = tid >> 3;
    const int ldc = (tid & 7) << 2;
    const int vsr = tid >> 3;          // s row 0..31
    const int vdc = (tid & 7) << 3;    // d base 0..56
    const int g4 = lane >> 2;
    const int g1 = lane & 3;

    float acc[2][4][4] = {};
    const int smax = t0 + 128;

    for (int s0 = 0; s0 < smax; s0 += 32) {
        float4 pv[4];
        #pragma unroll
        for (int r = 0; r < 4; r++)
            pv[r] = *(const float4*)(Pb + (size_t)(t0 + (r << 5) + ldr) * TLEN + s0 + ldc);
        float4 vv0 = *(const float4*)(Vb + (size_t)(s0 + vsr) * HD + vdc);
        float4 vv1 = *(const float4*)(Vb + (size_t)(s0 + vsr) * HD + vdc + 4);
        __syncthreads();
        #pragma unroll
        for (int r = 0; r < 4; r++) {
            uint32_t* pp = &Ps[(r << 5) + ldr][ldc];
            pp[0] = f2tf(pv[r].x); pp[1] = f2tf(pv[r].y); pp[2] = f2tf(pv[r].z); pp[3] = f2tf(pv[r].w);
        }
        Vs[vdc + 0][vsr] = f2tf(vv0.x); Vs[vdc + 1][vsr] = f2tf(vv0.y);
        Vs[vdc + 2][vsr] = f2tf(vv0.z); Vs[vdc + 3][vsr] = f2tf(vv0.w);
        Vs[vdc + 4][vsr] = f2tf(vv1.x); Vs[vdc + 5][vsr] = f2tf(vv1.y);
        Vs[vdc + 6][vsr] = f2tf(vv1.z); Vs[vdc + 7][vsr] = f2tf(vv1.w);
        __syncthreads();
        #pragma unroll
        for (int kk = 0; kk < 32; kk += 8) {
            uint32_t a[2][4], b[4][2];
            #pragma unroll
            for (int im = 0; im < 2; im++) {
                int mr = wm + (im << 4) + g4;
                a[im][0] = Ps[mr    ][kk + g1    ];
                a[im][1] = Ps[mr + 8][kk + g1    ];
                a[im][2] = Ps[mr    ][kk + g1 + 4];
                a[im][3] = Ps[mr + 8][kk + g1 + 4];
            }
            #pragma unroll
            for (int jn = 0; jn < 4; jn++) {
                int nr = wn + (jn << 3) + g4;
                b[jn][0] = Vs[nr][kk + g1    ];
                b[jn][1] = Vs[nr][kk + g1 + 4];
            }
            #pragma unroll
            for (int im = 0; im < 2; im++)
                #pragma unroll
                for (int jn = 0; jn < 4; jn++)
                    mma_tf32(acc[im][jn], a[im], b[jn]);
        }
    }

    const int b_ = bh >> 4, h = bh & 15;
    #pragma unroll
    for (int im = 0; im < 2; im++)
        #pragma unroll
        for (int jn = 0; jn < 4; jn++)
            #pragma unroll
            for (int ep = 0; ep < 2; ep++) {
                int t = t0 + wm + (im << 4) + g4 + (ep << 3);
                int d = wn + (jn << 3) + (g1 << 1);
                float* o = g_A + ((size_t)t * BATCH + b_) * EMBED + (h << 6) + d;
                *(float2*)o = make_float2(acc[im][jn][ep << 1], acc[im][jn][(ep << 1) + 1]);
            }
}

// ---------------------------------------------------------------------------
extern "C" void kernel_launch(void* const* d_in, const int* in_sizes, int n_in,
                              void* d_out, int out_size) {
    const float* query = (const float*)d_in[0];
    const int*   mask  = (const int*)d_in[1];   // numpy bool widened to int32
    const float* w_in  = (const float*)d_in[2];
    const float* b_in  = (const float*)d_in[3];
    const float* w_out = (const float*)d_in[4];
    const float* b_out = (const float*)d_in[5];

    float* outAttn = (float*)d_out;                                   // [T,B,E]
    float* outAvg  = (float*)d_out + (size_t)MROWS * EMBED;           // [B,T,S]

    k_gemm_tf32<0><<<dim3(24, 32), 256>>>(query, w_in, b_in, nullptr, EMBED);
    k_scores_mma<<<dim3(8, 8, 64), 256>>>();
    k_softmax  <<<dim3(1024, 64), 256>>>(mask);
    k_avg      <<<16384, 256>>>(outAvg);
    k_pv_mma   <<<dim3(8, 64), 256>>>();
    k_gemm_tf32<1><<<dim3(8, 32), 256>>>(nullptr, w_out, b_out, outAttn, EMBED);
}

// round 6
// speedup vs baseline: 2.8363x; 1.0589x over previous
#include <cuda_runtime.h>
#include <math.h>
#include <stdint.h>

#define TLEN   1024
#define BATCH  4
#define EMBED  1024
#define NH     16
#define HD     64
#define QSCALE 0.125f
#define MROWS  (TLEN * BATCH)   // 4096

// Scratch (static device globals — no cudaMalloc anywhere)
__device__ float g_Q[BATCH * NH * TLEN * HD];                 // [b,h,t,d], pre-scaled
__device__ float g_K[BATCH * NH * TLEN * HD];
__device__ float g_V[BATCH * NH * TLEN * HD];
__device__ float g_P[(size_t)BATCH * NH * TLEN * TLEN];       // scores -> probs
__device__ float g_A[MROWS * EMBED];                          // attention context [t,b,e]

__device__ __forceinline__ uint32_t f2tf(float f) {
    uint32_t u;
    asm("cvt.rna.tf32.f32 %0, %1;" : "=r"(u) : "f"(f));
    return u;
}

__device__ __forceinline__ void mma_tf32(float* d, const uint32_t* a, const uint32_t* b) {
    asm volatile(
        "mma.sync.aligned.m16n8k8.row.col.f32.tf32.tf32.f32 "
        "{%0,%1,%2,%3}, {%4,%5,%6,%7}, {%8,%9}, {%0,%1,%2,%3};"
        : "+f"(d[0]), "+f"(d[1]), "+f"(d[2]), "+f"(d[3])
        : "r"(a[0]), "r"(a[1]), "r"(a[2]), "r"(a[3]), "r"(b[0]), "r"(b[1]));
}

// ---------------------------------------------------------------------------
// TF32 tensor-core GEMM: C[M,N] = A[M,K] @ B[N,K]^T + bias
// CTA 128x128, BK=32, 8 warps (2m x 4n), warp tile 64x32, mma m16n8k8.
// Software-pipelined: global loads for step k+1 issued before MMAs of step k.
// EPI=0: A=query, scatter into g_Q/g_K/g_V. EPI=1: A=g_A (device symbol), C.
// ---------------------------------------------------------------------------
template <int EPI>
__global__ __launch_bounds__(256) void k_gemm_tf32(const float* __restrict__ Ain,
                                                   const float* __restrict__ B,
                                                   const float* __restrict__ bias,
                                                   float* __restrict__ C,
                                                   int K) {
    const float* A = (EPI == 0) ? Ain : (const float*)g_A;
    __shared__ uint32_t As[128][36];
    __shared__ uint32_t Bs[128][36];
    const int tid  = threadIdx.x;
    const int lane = tid & 31;
    const int wid  = tid >> 5;
    const int wm   = (wid & 1) << 6;
    const int wn   = (wid >> 1) << 5;
    const int m0   = blockIdx.y << 7;
    const int n0   = blockIdx.x << 7;
    const int ldr = tid >> 3;
    const int ldc = (tid & 7) << 2;
    const int g4 = lane >> 2;
    const int g1 = lane & 3;

    float acc[4][4][4] = {};
    float4 av[4], bv[4];

    const float* Abase = A + (size_t)(m0 + ldr) * K + ldc;
    const float* Bbase = B + (size_t)(n0 + ldr) * K + ldc;

    #pragma unroll
    for (int r = 0; r < 4; r++) {
        av[r] = *(const float4*)(Abase + (size_t)(r << 5) * K);
        bv[r] = *(const float4*)(Bbase + (size_t)(r << 5) * K);
    }

    for (int k0 = 0; k0 < K; k0 += 32) {
        __syncthreads();
        #pragma unroll
        for (int r = 0; r < 4; r++) {
            uint32_t* pa = &As[(r << 5) + ldr][ldc];
            uint32_t* pb = &Bs[(r << 5) + ldr][ldc];
            pa[0] = f2tf(av[r].x); pa[1] = f2tf(av[r].y); pa[2] = f2tf(av[r].z); pa[3] = f2tf(av[r].w);
            pb[0] = f2tf(bv[r].x); pb[1] = f2tf(bv[r].y); pb[2] = f2tf(bv[r].z); pb[3] = f2tf(bv[r].w);
        }
        __syncthreads();
        if (k0 + 32 < K) {
            #pragma unroll
            for (int r = 0; r < 4; r++) {
                av[r] = *(const float4*)(Abase + (size_t)(r << 5) * K + k0 + 32);
                bv[r] = *(const float4*)(Bbase + (size_t)(r << 5) * K + k0 + 32);
            }
        }
        #pragma unroll
        for (int kk = 0; kk < 32; kk += 8) {
            uint32_t a[4][4], b[4][2];
            #pragma unroll
            for (int im = 0; im < 4; im++) {
                int mr = wm + (im << 4) + g4;
                a[im][0] = As[mr    ][kk + g1    ];
                a[im][1] = As[mr + 8][kk + g1    ];
                a[im][2] = As[mr    ][kk + g1 + 4];
                a[im][3] = As[mr + 8][kk + g1 + 4];
            }
            #pragma unroll
            for (int jn = 0; jn < 4; jn++) {
                int nr = wn + (jn << 3) + g4;
                b[jn][0] = Bs[nr][kk + g1    ];
                b[jn][1] = Bs[nr][kk + g1 + 4];
            }
            #pragma unroll
            for (int im = 0; im < 4; im++)
                #pragma unroll
                for (int jn = 0; jn < 4; jn++)
                    mma_tf32(acc[im][jn], a[im], b[jn]);
        }
    }

    #pragma unroll
    for (int im = 0; im < 4; im++)
        #pragma unroll
        for (int jn = 0; jn < 4; jn++)
            #pragma unroll
            for (int e = 0; e < 4; e++) {
                int m = m0 + wm + (im << 4) + g4 + ((e >> 1) << 3);
                int n = n0 + wn + (jn << 3) + (g1 << 1) + (e & 1);
                float v = acc[im][jn][e] + bias[n];
                if (EPI == 0) {
                    int t = m >> 2, bb = m & 3;
                    int c = n >> 10;
                    int ee = n & 1023;
                    int h = ee >> 6, d = ee & 63;
                    int idx = (((bb << 4) + h) * TLEN + t) * HD + d;
                    if (c == 0)      g_Q[idx] = v * QSCALE;
                    else if (c == 1) g_K[idx] = v;
                    else             g_V[idx] = v;
                } else {
                    C[(size_t)m * EMBED + n] = v;
                }
            }
}

// ---------------------------------------------------------------------------
// K2a: scores = Q @ K^T per (b,h), TF32 MMA, pipelined. 128x128 tiles,
// K=64 (2 x BK=32). Tiles entirely above the causal diagonal skipped.
// ---------------------------------------------------------------------------
__global__ __launch_bounds__(256) void k_scores_mma() {
    const int t0 = blockIdx.y << 7;
    const int s0 = blockIdx.x << 7;
    if (s0 > t0 + 127) return;        // structurally masked tile
    __shared__ uint32_t Qs[128][36];
    __shared__ uint32_t Ks[128][36];
    const int bh = blockIdx.z;
    const float* Qb = g_Q + (size_t)bh * TLEN * HD;
    const float* Kb = g_K + (size_t)bh * TLEN * HD;
    const int tid  = threadIdx.x;
    const int lane = tid & 31;
    const int wid  = tid >> 5;
    const int wm   = (wid & 1) << 6;
    const int wn   = (wid >> 1) << 5;
    const int ldr = tid >> 3;
    const int ldc = (tid & 7) << 2;
    const int g4 = lane >> 2;
    const int g1 = lane & 3;

    float acc[4][4][4] = {};
    float4 qv[4], kv[4];

    #pragma unroll
    for (int r = 0; r < 4; r++) {
        qv[r] = *(const float4*)(Qb + (size_t)(t0 + (r << 5) + ldr) * HD + ldc);
        kv[r] = *(const float4*)(Kb + (size_t)(s0 + (r << 5) + ldr) * HD + ldc);
    }

    #pragma unroll
    for (int k0 = 0; k0 < 64; k0 += 32) {
        __syncthreads();
        #pragma unroll
        for (int r = 0; r < 4; r++) {
            uint32_t* pq = &Qs[(r << 5) + ldr][ldc];
            uint32_t* pk = &Ks[(r << 5) + ldr][ldc];
            pq[0] = f2tf(qv[r].x); pq[1] = f2tf(qv[r].y); pq[2] = f2tf(qv[r].z); pq[3] = f2tf(qv[r].w);
            pk[0] = f2tf(kv[r].x); pk[1] = f2tf(kv[r].y); pk[2] = f2tf(kv[r].z); pk[3] = f2tf(kv[r].w);
        }
        __syncthreads();
        if (k0 == 0) {
            #pragma unroll
            for (int r = 0; r < 4; r++) {
                qv[r] = *(const float4*)(Qb + (size_t)(t0 + (r << 5) + ldr) * HD + 32 + ldc);
                kv[r] = *(const float4*)(Kb + (size_t)(s0 + (r << 5) + ldr) * HD + 32 + ldc);
            }
        }
        #pragma unroll
        for (int kk = 0; kk < 32; kk += 8) {
            uint32_t a[4][4], b[4][2];
            #pragma unroll
            for (int im = 0; im < 4; im++) {
                int mr = wm + (im << 4) + g4;
                a[im][0] = Qs[mr    ][kk + g1    ];
                a[im][1] = Qs[mr + 8][kk + g1    ];
                a[im][2] = Qs[mr    ][kk + g1 + 4];
                a[im][3] = Qs[mr + 8][kk + g1 + 4];
            }
            #pragma unroll
            for (int jn = 0; jn < 4; jn++) {
                int nr = wn + (jn << 3) + g4;
                b[jn][0] = Ks[nr][kk + g1    ];
                b[jn][1] = Ks[nr][kk + g1 + 4];
            }
            #pragma unroll
            for (int im = 0; im < 4; im++)
                #pragma unroll
                for (int jn = 0; jn < 4; jn++)
                    mma_tf32(acc[im][jn], a[im], b[jn]);
        }
    }

    float* out = g_P + (size_t)bh * TLEN * TLEN;
    #pragma unroll
    for (int im = 0; im < 4; im++)
        #pragma unroll
        for (int jn = 0; jn < 4; jn++)
            #pragma unroll
            for (int ep = 0; ep < 2; ep++) {
                int t = t0 + wm + (im << 4) + g4 + (ep << 3);
                int s = s0 + wn + (jn << 3) + (g1 << 1);
                float2 v2 = make_float2(acc[im][jn][ep << 1], acc[im][jn][(ep << 1) + 1]);
                *(float2*)(out + (size_t)t * TLEN + s) = v2;
            }
}

// ---------------------------------------------------------------------------
// K2b: triangular row softmax. Loads only s <= t (predicated); writes
// s < send = ((t>>7)+1)*128 — exactly the range PV and avg consume.
// Masked entries -> exactly 0.
// ---------------------------------------------------------------------------
__global__ __launch_bounds__(256) void k_softmax(const int* __restrict__ pad) {
    const int t  = blockIdx.x;
    const int bh = blockIdx.y;
    const int b  = bh >> 4;
    const int send = (((t >> 7) + 1) << 7);   // 128..1024
    float* row = g_P + ((size_t)bh * TLEN + t) * TLEN;
    const int tid = threadIdx.x;
    float v[4];
    bool ok[4];
    #pragma unroll
    for (int k = 0; k < 4; k++) {
        int s = tid + (k << 8);
        bool in = (s <= t) && (pad[b * TLEN + s] == 0);
        ok[k] = in;
        v[k] = in ? row[s] : -1e30f;
    }
    __shared__ float redm[8];
    __shared__ float reds[8];
    float m = fmaxf(fmaxf(v[0], v[1]), fmaxf(v[2], v[3]));
    #pragma unroll
    for (int o = 16; o; o >>= 1) m = fmaxf(m, __shfl_xor_sync(0xffffffffu, m, o));
    if ((tid & 31) == 0) redm[tid >> 5] = m;
    __syncthreads();
    m = fmaxf(fmaxf(fmaxf(redm[0], redm[1]), fmaxf(redm[2], redm[3])),
              fmaxf(fmaxf(redm[4], redm[5]), fmaxf(redm[6], redm[7])));
    float e[4], sum = 0.f;
    #pragma unroll
    for (int k = 0; k < 4; k++) {
        e[k] = ok[k] ? __expf(v[k] - m) : 0.f;
        sum += e[k];
    }
    #pragma unroll
    for (int o = 16; o; o >>= 1) sum += __shfl_xor_sync(0xffffffffu, sum, o);
    if ((tid & 31) == 0) reds[tid >> 5] = sum;
    __syncthreads();
    sum = reds[0] + reds[1] + reds[2] + reds[3] + reds[4] + reds[5] + reds[6] + reds[7];
    float inv = 1.f / sum;
    #pragma unroll
    for (int k = 0; k < 4; k++) {
        int s = tid + (k << 8);
        if (s < send) row[s] = e[k] * inv;
    }
}

// ---------------------------------------------------------------------------
// K2c: avg_weights[b,t,s]: 0 for s>t (causal zeros, no read needed);
// else mean over 16 heads.
// ---------------------------------------------------------------------------
__global__ __launch_bounds__(256) void k_avg(float* __restrict__ outAvg) {
    const int idx = blockIdx.x * 256 + threadIdx.x;
    const int s = idx & 1023;
    const int t = (idx >> 10) & 1023;
    const int b = idx >> 20;
    if (s > t) { outAvg[idx] = 0.f; return; }
    const float* base = g_P + ((size_t)(b << 4) * TLEN + t) * TLEN + s;
    float sum = 0.f;
    #pragma unroll
    for (int h = 0; h < 16; h++)
        sum += base[(size_t)h * TLEN * TLEN];
    outAvg[idx] = sum * 0.0625f;
}

// ---------------------------------------------------------------------------
// K2d: context = P @ V per (b,h), TF32 MMA, pipelined. CTA = 128 t x 64 d,
// s-loop truncated at causal diagonal block. 8 warps (4m x 2n).
// ---------------------------------------------------------------------------
__global__ __launch_bounds__(256) void k_pv_mma() {
    __shared__ uint32_t Ps[128][36];
    __shared__ uint32_t Vs[64][36];
    const int t0 = blockIdx.x << 7;
    const int bh = blockIdx.y;
    const float* Pb = g_P + (size_t)bh * TLEN * TLEN;
    const float* Vb = g_V + (size_t)bh * TLEN * HD;
    const int tid  = threadIdx.x;
    const int lane = tid & 31;
    const int wid  = tid >> 5;
    const int wm   = (wid & 3) << 5;
    const int wn   = (wid >> 2) << 5;
    const int ldr = tid >> 3;
    const int ldc = (tid & 7) << 2;
    const int vsr = tid >> 3;
    const int vdc = (tid & 7) << 3;
    const int g4 = lane >> 2;
    const int g1 = lane & 3;

    float acc[2][4][4] = {};
    const int smax = t0 + 128;
    float4 pv[4], vv0, vv1;

    #pragma unroll
    for (int r = 0; r < 4; r++)
        pv[r] = *(const float4*)(Pb + (size_t)(t0 + (r << 5) + ldr) * TLEN + ldc);
    vv0 = *(const float4*)(Vb + (size_t)vsr * HD + vdc);
    vv1 = *(const float4*)(Vb + (size_t)vsr * HD + vdc + 4);

    for (int s0 = 0; s0 < smax; s0 += 32) {
        __syncthreads();
        #pragma unroll
        for (int r = 0; r < 4; r++) {
            uint32_t* pp = &Ps[(r << 5) + ldr][ldc];
            pp[0] = f2tf(pv[r].x); pp[1] = f2tf(pv[r].y); pp[2] = f2tf(pv[r].z); pp[3] = f2tf(pv[r].w);
        }
        Vs[vdc + 0][vsr] = f2tf(vv0.x); Vs[vdc + 1][vsr] = f2tf(vv0.y);
        Vs[vdc + 2][vsr] = f2tf(vv0.z); Vs[vdc + 3][vsr] = f2tf(vv0.w);
        Vs[vdc + 4][vsr] = f2tf(vv1.x); Vs[vdc + 5][vsr] = f2tf(vv1.y);
        Vs[vdc + 6][vsr] = f2tf(vv1.z); Vs[vdc + 7][vsr] = f2tf(vv1.w);
        __syncthreads();
        if (s0 + 32 < smax) {
            int sn = s0 + 32;
            #pragma unroll
            for (int r = 0; r < 4; r++)
                pv[r] = *(const float4*)(Pb + (size_t)(t0 + (r << 5) + ldr) * TLEN + sn + ldc);
            vv0 = *(const float4*)(Vb + (size_t)(sn + vsr) * HD + vdc);
            vv1 = *(const float4*)(Vb + (size_t)(sn + vsr) * HD + vdc + 4);
        }
        #pragma unroll
        for (int kk = 0; kk < 32; kk += 8) {
            uint32_t a[2][4], b[4][2];
            #pragma unroll
            for (int im = 0; im < 2; im++) {
                int mr = wm + (im << 4) + g4;
                a[im][0] = Ps[mr    ][kk + g1    ];
                a[im][1] = Ps[mr + 8][kk + g1    ];
                a[im][2] = Ps[mr    ][kk + g1 + 4];
                a[im][3] = Ps[mr + 8][kk + g1 + 4];
            }
            #pragma unroll
            for (int jn = 0; jn < 4; jn++) {
                int nr = wn + (jn << 3) + g4;
                b[jn][0] = Vs[nr][kk + g1    ];
                b[jn][1] = Vs[nr][kk + g1 + 4];
            }
            #pragma unroll
            for (int im = 0; im < 2; im++)
                #pragma unroll
                for (int jn = 0; jn < 4; jn++)
                    mma_tf32(acc[im][jn], a[im], b[jn]);
        }
    }

    const int b_ = bh >> 4, h = bh & 15;
    #pragma unroll
    for (int im = 0; im < 2; im++)
        #pragma unroll
        for (int jn = 0; jn < 4; jn++)
            #pragma unroll
            for (int ep = 0; ep < 2; ep++) {
                int t = t0 + wm + (im << 4) + g4 + (ep << 3);
                int d = wn + (jn << 3) + (g1 << 1);
                float* o = g_A + ((size_t)t * BATCH + b_) * EMBED + (h << 6) + d;
                *(float2*)o = make_float2(acc[im][jn][ep << 1], acc[im][jn][(ep << 1) + 1]);
            }
}

// ---------------------------------------------------------------------------
extern "C" void kernel_launch(void* const* d_in, const int* in_sizes, int n_in,
                              void* d_out, int out_size) {
    const float* query = (const float*)d_in[0];
    const int*   mask  = (const int*)d_in[1];   // numpy bool widened to int32
    const float* w_in  = (const float*)d_in[2];
    const float* b_in  = (const float*)d_in[3];
    const float* w_out = (const float*)d_in[4];
    const float* b_out = (const float*)d_in[5];

    float* outAttn = (float*)d_out;                                   // [T,B,E]
    float* outAvg  = (float*)d_out + (size_t)MROWS * EMBED;           // [B,T,S]

    k_gemm_tf32<0><<<dim3(24, 32), 256>>>(query, w_in, b_in, nullptr, EMBED);
    k_scores_mma<<<dim3(8, 8, 64), 256>>>();
    k_softmax  <<<dim3(1024, 64), 256>>>(mask);
    k_avg      <<<16384, 256>>>(outAvg);
    k_pv_mma   <<<dim3(8, 64), 256>>>();
    k_gemm_tf32<1><<<dim3(8, 32), 256>>>(nullptr, w_out, b_out, outAttn, EMBED);
}

// round 7
// speedup vs baseline: 2.8677x; 1.0111x over previous
#include <cuda_runtime.h>
#include <math.h>
#include <stdint.h>

#define TLEN   1024
#define BATCH  4
#define EMBED  1024
#define NH     16
#define HD     64
#define QSCALE 0.125f
#define MROWS  (TLEN * BATCH)   // 4096

// Scratch (static device globals — no cudaMalloc anywhere)
__device__ float g_Q[BATCH * NH * TLEN * HD];                 // [b,h,t,d], pre-scaled
__device__ float g_K[BATCH * NH * TLEN * HD];
__device__ float g_V[BATCH * NH * TLEN * HD];
__device__ float g_P[(size_t)BATCH * NH * TLEN * TLEN];       // scores -> probs
__device__ float g_A[MROWS * EMBED];                          // attention context [t,b,e]

__device__ __forceinline__ uint32_t f2tf(float f) {
    uint32_t u;
    asm("cvt.rna.tf32.f32 %0, %1;" : "=r"(u) : "f"(f));
    return u;
}

__device__ __forceinline__ void mma_tf32(float* d, const uint32_t* a, const uint32_t* b) {
    asm volatile(
        "mma.sync.aligned.m16n8k8.row.col.f32.tf32.tf32.f32 "
        "{%0,%1,%2,%3}, {%4,%5,%6,%7}, {%8,%9}, {%0,%1,%2,%3};"
        : "+f"(d[0]), "+f"(d[1]), "+f"(d[2]), "+f"(d[3])
        : "r"(a[0]), "r"(a[1]), "r"(a[2]), "r"(a[3]), "r"(b[0]), "r"(b[1]));
}

// ---------------------------------------------------------------------------
// TF32 tensor-core GEMM: C[M,N] = A[M,K] @ B[N,K]^T + bias
// CTA 128x128, BK=32, 8 warps (2m x 4n), warp tile 64x32, mma m16n8k8.
// DOUBLE-BUFFERED dynamic smem: one barrier per BK step; MMA(cur) overlaps
// LDG(next) and STS(next).
// EPI=0: A=query, scatter into g_Q/g_K/g_V. EPI=1: A=g_A (device symbol), C.
// ---------------------------------------------------------------------------
#define GEMM_SMEM_WORDS (4 * 128 * 36)   // 2 bufs x (As+Bs) x 128x36
#define AS(buf, r, c) As[(buf) * 4608 + (r) * 36 + (c)]
#define BS(buf, r, c) Bs[(buf) * 4608 + (r) * 36 + (c)]

template <int EPI>
__global__ __launch_bounds__(256) void k_gemm_tf32(const float* __restrict__ Ain,
                                                   const float* __restrict__ B,
                                                   const float* __restrict__ bias,
                                                   float* __restrict__ C,
                                                   int K) {
    const float* A = (EPI == 0) ? Ain : (const float*)g_A;
    extern __shared__ uint32_t smraw[];
    uint32_t* As = smraw;
    uint32_t* Bs = smraw + 2 * 4608;
    const int tid  = threadIdx.x;
    const int lane = tid & 31;
    const int wid  = tid >> 5;
    const int wm   = (wid & 1) << 6;
    const int wn   = (wid >> 1) << 5;
    const int m0   = blockIdx.y << 7;
    const int n0   = blockIdx.x << 7;
    const int ldr = tid >> 3;
    const int ldc = (tid & 7) << 2;
    const int g4 = lane >> 2;
    const int g1 = lane & 3;

    float acc[4][4][4] = {};
    float4 av[4], bv[4];

    const float* Abase = A + (size_t)(m0 + ldr) * K + ldc;
    const float* Bbase = B + (size_t)(n0 + ldr) * K + ldc;

    #pragma unroll
    for (int r = 0; r < 4; r++) {
        av[r] = *(const float4*)(Abase + (size_t)(r << 5) * K);
        bv[r] = *(const float4*)(Bbase + (size_t)(r << 5) * K);
    }
    #pragma unroll
    for (int r = 0; r < 4; r++) {
        uint32_t* pa = &AS(0, (r << 5) + ldr, ldc);
        uint32_t* pb = &BS(0, (r << 5) + ldr, ldc);
        pa[0] = f2tf(av[r].x); pa[1] = f2tf(av[r].y); pa[2] = f2tf(av[r].z); pa[3] = f2tf(av[r].w);
        pb[0] = f2tf(bv[r].x); pb[1] = f2tf(bv[r].y); pb[2] = f2tf(bv[r].z); pb[3] = f2tf(bv[r].w);
    }
    __syncthreads();

    int cur = 0;
    for (int k0 = 0; k0 < K; k0 += 32) {
        const bool has_next = (k0 + 32 < K);
        if (has_next) {
            #pragma unroll
            for (int r = 0; r < 4; r++) {
                av[r] = *(const float4*)(Abase + (size_t)(r << 5) * K + k0 + 32);
                bv[r] = *(const float4*)(Bbase + (size_t)(r << 5) * K + k0 + 32);
            }
        }
        #pragma unroll
        for (int kk = 0; kk < 32; kk += 8) {
            uint32_t a[4][4], b[4][2];
            #pragma unroll
            for (int im = 0; im < 4; im++) {
                int mr = wm + (im << 4) + g4;
                a[im][0] = AS(cur, mr    , kk + g1    );
                a[im][1] = AS(cur, mr + 8, kk + g1    );
                a[im][2] = AS(cur, mr    , kk + g1 + 4);
                a[im][3] = AS(cur, mr + 8, kk + g1 + 4);
            }
            #pragma unroll
            for (int jn = 0; jn < 4; jn++) {
                int nr = wn + (jn << 3) + g4;
                b[jn][0] = BS(cur, nr, kk + g1    );
                b[jn][1] = BS(cur, nr, kk + g1 + 4);
            }
            #pragma unroll
            for (int im = 0; im < 4; im++)
                #pragma unroll
                for (int jn = 0; jn < 4; jn++)
                    mma_tf32(acc[im][jn], a[im], b[jn]);
        }
        if (has_next) {
            int nxt = cur ^ 1;
            #pragma unroll
            for (int r = 0; r < 4; r++) {
                uint32_t* pa = &AS(nxt, (r << 5) + ldr, ldc);
                uint32_t* pb = &BS(nxt, (r << 5) + ldr, ldc);
                pa[0] = f2tf(av[r].x); pa[1] = f2tf(av[r].y); pa[2] = f2tf(av[r].z); pa[3] = f2tf(av[r].w);
                pb[0] = f2tf(bv[r].x); pb[1] = f2tf(bv[r].y); pb[2] = f2tf(bv[r].z); pb[3] = f2tf(bv[r].w);
            }
            __syncthreads();
        }
        cur ^= 1;
    }

    #pragma unroll
    for (int im = 0; im < 4; im++)
        #pragma unroll
        for (int jn = 0; jn < 4; jn++)
            #pragma unroll
            for (int e = 0; e < 4; e++) {
                int m = m0 + wm + (im << 4) + g4 + ((e >> 1) << 3);
                int n = n0 + wn + (jn << 3) + (g1 << 1) + (e & 1);
                float v = acc[im][jn][e] + bias[n];
                if (EPI == 0) {
                    int t = m >> 2, bb = m & 3;
                    int c = n >> 10;
                    int ee = n & 1023;
                    int h = ee >> 6, d = ee & 63;
                    int idx = (((bb << 4) + h) * TLEN + t) * HD + d;
                    if (c == 0)      g_Q[idx] = v * QSCALE;
                    else if (c == 1) g_K[idx] = v;
                    else             g_V[idx] = v;
                } else {
                    C[(size_t)m * EMBED + n] = v;
                }
            }
}

// ---------------------------------------------------------------------------
// K2a: scores = Q @ K^T per (b,h), TF32 MMA, pipelined (2 BK steps only).
// Tiles entirely above the causal diagonal skipped.
// ---------------------------------------------------------------------------
__global__ __launch_bounds__(256) void k_scores_mma() {
    const int t0 = blockIdx.y << 7;
    const int s0 = blockIdx.x << 7;
    if (s0 > t0 + 127) return;
    __shared__ uint32_t Qs[128][36];
    __shared__ uint32_t Ks[128][36];
    const int bh = blockIdx.z;
    const float* Qb = g_Q + (size_t)bh * TLEN * HD;
    const float* Kb = g_K + (size_t)bh * TLEN * HD;
    const int tid  = threadIdx.x;
    const int lane = tid & 31;
    const int wid  = tid >> 5;
    const int wm   = (wid & 1) << 6;
    const int wn   = (wid >> 1) << 5;
    const int ldr = tid >> 3;
    const int ldc = (tid & 7) << 2;
    const int g4 = lane >> 2;
    const int g1 = lane & 3;

    float acc[4][4][4] = {};
    float4 qv[4], kv[4];

    #pragma unroll
    for (int r = 0; r < 4; r++) {
        qv[r] = *(const float4*)(Qb + (size_t)(t0 + (r << 5) + ldr) * HD + ldc);
        kv[r] = *(const float4*)(Kb + (size_t)(s0 + (r << 5) + ldr) * HD + ldc);
    }

    #pragma unroll
    for (int k0 = 0; k0 < 64; k0 += 32) {
        __syncthreads();
        #pragma unroll
        for (int r = 0; r < 4; r++) {
            uint32_t* pq = &Qs[(r << 5) + ldr][ldc];
            uint32_t* pk = &Ks[(r << 5) + ldr][ldc];
            pq[0] = f2tf(qv[r].x); pq[1] = f2tf(qv[r].y); pq[2] = f2tf(qv[r].z); pq[3] = f2tf(qv[r].w);
            pk[0] = f2tf(kv[r].x); pk[1] = f2tf(kv[r].y); pk[2] = f2tf(kv[r].z); pk[3] = f2tf(kv[r].w);
        }
        __syncthreads();
        if (k0 == 0) {
            #pragma unroll
            for (int r = 0; r < 4; r++) {
                qv[r] = *(const float4*)(Qb + (size_t)(t0 + (r << 5) + ldr) * HD + 32 + ldc);
                kv[r] = *(const float4*)(Kb + (size_t)(s0 + (r << 5) + ldr) * HD + 32 + ldc);
            }
        }
        #pragma unroll
        for (int kk = 0; kk < 32; kk += 8) {
            uint32_t a[4][4], b[4][2];
            #pragma unroll
            for (int im = 0; im < 4; im++) {
                int mr = wm + (im << 4) + g4;
                a[im][0] = Qs[mr    ][kk + g1    ];
                a[im][1] = Qs[mr + 8][kk + g1    ];
                a[im][2] = Qs[mr    ][kk + g1 + 4];
                a[im][3] = Qs[mr + 8][kk + g1 + 4];
            }
            #pragma unroll
            for (int jn = 0; jn < 4; jn++) {
                int nr = wn + (jn << 3) + g4;
                b[jn][0] = Ks[nr][kk + g1    ];
                b[jn][1] = Ks[nr][kk + g1 + 4];
            }
            #pragma unroll
            for (int im = 0; im < 4; im++)
                #pragma unroll
                for (int jn = 0; jn < 4; jn++)
                    mma_tf32(acc[im][jn], a[im], b[jn]);
        }
    }

    float* out = g_P + (size_t)bh * TLEN * TLEN;
    #pragma unroll
    for (int im = 0; im < 4; im++)
        #pragma unroll
        for (int jn = 0; jn < 4; jn++)
            #pragma unroll
            for (int ep = 0; ep < 2; ep++) {
                int t = t0 + wm + (im << 4) + g4 + (ep << 3);
                int s = s0 + wn + (jn << 3) + (g1 << 1);
                float2 v2 = make_float2(acc[im][jn][ep << 1], acc[im][jn][(ep << 1) + 1]);
                *(float2*)(out + (size_t)t * TLEN + s) = v2;
            }
}

// ---------------------------------------------------------------------------
// K2b: triangular row softmax (loads s<=t; writes s<send). Exact zeros.
// ---------------------------------------------------------------------------
__global__ __launch_bounds__(256) void k_softmax(const int* __restrict__ pad) {
    const int t  = blockIdx.x;
    const int bh = blockIdx.y;
    const int b  = bh >> 4;
    const int send = (((t >> 7) + 1) << 7);
    float* row = g_P + ((size_t)bh * TLEN + t) * TLEN;
    const int tid = threadIdx.x;
    float v[4];
    bool ok[4];
    #pragma unroll
    for (int k = 0; k < 4; k++) {
        int s = tid + (k << 8);
        bool in = (s <= t) && (pad[b * TLEN + s] == 0);
        ok[k] = in;
        v[k] = in ? row[s] : -1e30f;
    }
    __shared__ float redm[8];
    __shared__ float reds[8];
    float m = fmaxf(fmaxf(v[0], v[1]), fmaxf(v[2], v[3]));
    #pragma unroll
    for (int o = 16; o; o >>= 1) m = fmaxf(m, __shfl_xor_sync(0xffffffffu, m, o));
    if ((tid & 31) == 0) redm[tid >> 5] = m;
    __syncthreads();
    m = fmaxf(fmaxf(fmaxf(redm[0], redm[1]), fmaxf(redm[2], redm[3])),
              fmaxf(fmaxf(redm[4], redm[5]), fmaxf(redm[6], redm[7])));
    float e[4], sum = 0.f;
    #pragma unroll
    for (int k = 0; k < 4; k++) {
        e[k] = ok[k] ? __expf(v[k] - m) : 0.f;
        sum += e[k];
    }
    #pragma unroll
    for (int o = 16; o; o >>= 1) sum += __shfl_xor_sync(0xffffffffu, sum, o);
    if ((tid & 31) == 0) reds[tid >> 5] = sum;
    __syncthreads();
    sum = reds[0] + reds[1] + reds[2] + reds[3] + reds[4] + reds[5] + reds[6] + reds[7];
    float inv = 1.f / sum;
    #pragma unroll
    for (int k = 0; k < 4; k++) {
        int s = tid + (k << 8);
        if (s < send) row[s] = e[k] * inv;
    }
}

// ---------------------------------------------------------------------------
// K2c: avg_weights: 0 for s>t; else mean over 16 heads. Runs on side stream.
// ---------------------------------------------------------------------------
__global__ __launch_bounds__(256) void k_avg(float* __restrict__ outAvg) {
    const int idx = blockIdx.x * 256 + threadIdx.x;
    const int s = idx & 1023;
    const int t = (idx >> 10) & 1023;
    const int b = idx >> 20;
    if (s > t) { outAvg[idx] = 0.f; return; }
    const float* base = g_P + ((size_t)(b << 4) * TLEN + t) * TLEN + s;
    float sum = 0.f;
    #pragma unroll
    for (int h = 0; h < 16; h++)
        sum += base[(size_t)h * TLEN * TLEN];
    outAvg[idx] = sum * 0.0625f;
}

// ---------------------------------------------------------------------------
// K2d: context = P @ V per (b,h), TF32 MMA, DOUBLE-BUFFERED dynamic smem.
// s-loop truncated at causal diagonal block. 8 warps (4m x 2n).
// ---------------------------------------------------------------------------
#define PV_SMEM_WORDS (2 * 4608 + 2 * 2304)
#define PS(buf, r, c) Ps[(buf) * 4608 + (r) * 36 + (c)]
#define VS(buf, r, c) Vs[(buf) * 2304 + (r) * 36 + (c)]

__global__ __launch_bounds__(256) void k_pv_mma() {
    extern __shared__ uint32_t smraw[];
    uint32_t* Ps = smraw;
    uint32_t* Vs = smraw + 2 * 4608;
    const int t0 = blockIdx.x << 7;
    const int bh = blockIdx.y;
    const float* Pb = g_P + (size_t)bh * TLEN * TLEN;
    const float* Vb = g_V + (size_t)bh * TLEN * HD;
    const int tid  = threadIdx.x;
    const int lane = tid & 31;
    const int wid  = tid >> 5;
    const int wm   = (wid & 3) << 5;
    const int wn   = (wid >> 2) << 5;
    const int ldr = tid >> 3;
    const int ldc = (tid & 7) << 2;
    const int vsr = tid >> 3;
    const int vdc = (tid & 7) << 3;
    const int g4 = lane >> 2;
    const int g1 = lane & 3;

    float acc[2][4][4] = {};
    const int smax = t0 + 128;
    float4 pv[4], vv0, vv1;

    #pragma unroll
    for (int r = 0; r < 4; r++)
        pv[r] = *(const float4*)(Pb + (size_t)(t0 + (r << 5) + ldr) * TLEN + ldc);
    vv0 = *(const float4*)(Vb + (size_t)vsr * HD + vdc);
    vv1 = *(const float4*)(Vb + (size_t)vsr * HD + vdc + 4);

    #pragma unroll
    for (int r = 0; r < 4; r++) {
        uint32_t* pp = &PS(0, (r << 5) + ldr, ldc);
        pp[0] = f2tf(pv[r].x); pp[1] = f2tf(pv[r].y); pp[2] = f2tf(pv[r].z); pp[3] = f2tf(pv[r].w);
    }
    VS(0, vdc + 0, vsr) = f2tf(vv0.x); VS(0, vdc + 1, vsr) = f2tf(vv0.y);
    VS(0, vdc + 2, vsr) = f2tf(vv0.z); VS(0, vdc + 3, vsr) = f2tf(vv0.w);
    VS(0, vdc + 4, vsr) = f2tf(vv1.x); VS(0, vdc + 5, vsr) = f2tf(vv1.y);
    VS(0, vdc + 6, vsr) = f2tf(vv1.z); VS(0, vdc + 7, vsr) = f2tf(vv1.w);
    __syncthreads();

    int cur = 0;
    for (int s0 = 0; s0 < smax; s0 += 32) {
        const bool has_next = (s0 + 32 < smax);
        if (has_next) {
            int sn = s0 + 32;
            #pragma unroll
            for (int r = 0; r < 4; r++)
                pv[r] = *(const float4*)(Pb + (size_t)(t0 + (r << 5) + ldr) * TLEN + sn + ldc);
            vv0 = *(const float4*)(Vb + (size_t)(sn + vsr) * HD + vdc);
            vv1 = *(const float4*)(Vb + (size_t)(sn + vsr) * HD + vdc + 4);
        }
        #pragma unroll
        for (int kk = 0; kk < 32; kk += 8) {
            uint32_t a[2][4], b[4][2];
            #pragma unroll
            for (int im = 0; im < 2; im++) {
                int mr = wm + (im << 4) + g4;
                a[im][0] = PS(cur, mr    , kk + g1    );
                a[im][1] = PS(cur, mr + 8, kk + g1    );
                a[im][2] = PS(cur, mr    , kk + g1 + 4);
                a[im][3] = PS(cur, mr + 8, kk + g1 + 4);
            }
            #pragma unroll
            for (int jn = 0; jn < 4; jn++) {
                int nr = wn + (jn << 3) + g4;
                b[jn][0] = VS(cur, nr, kk + g1    );
                b[jn][1] = VS(cur, nr, kk + g1 + 4);
            }
            #pragma unroll
            for (int im = 0; im < 2; im++)
                #pragma unroll
                for (int jn = 0; jn < 4; jn++)
                    mma_tf32(acc[im][jn], a[im], b[jn]);
        }
        if (has_next) {
            int nxt = cur ^ 1;
            #pragma unroll
            for (int r = 0; r < 4; r++) {
                uint32_t* pp = &PS(nxt, (r << 5) + ldr, ldc);
                pp[0] = f2tf(pv[r].x); pp[1] = f2tf(pv[r].y); pp[2] = f2tf(pv[r].z); pp[3] = f2tf(pv[r].w);
            }
            VS(nxt, vdc + 0, vsr) = f2tf(vv0.x); VS(nxt, vdc + 1, vsr) = f2tf(vv0.y);
            VS(nxt, vdc + 2, vsr) = f2tf(vv0.z); VS(nxt, vdc + 3, vsr) = f2tf(vv0.w);
            VS(nxt, vdc + 4, vsr) = f2tf(vv1.x); VS(nxt, vdc + 5, vsr) = f2tf(vv1.y);
            VS(nxt, vdc + 6, vsr) = f2tf(vv1.z); VS(nxt, vdc + 7, vsr) = f2tf(vv1.w);
            __syncthreads();
        }
        cur ^= 1;
    }

    const int b_ = bh >> 4, h = bh & 15;
    #pragma unroll
    for (int im = 0; im < 2; im++)
        #pragma unroll
        for (int jn = 0; jn < 4; jn++)
            #pragma unroll
            for (int ep = 0; ep < 2; ep++) {
                int t = t0 + wm + (im << 4) + g4 + (ep << 3);
                int d = wn + (jn << 3) + (g1 << 1);
                float* o = g_A + ((size_t)t * BATCH + b_) * EMBED + (h << 6) + d;
                *(float2*)o = make_float2(acc[im][jn][ep << 1], acc[im][jn][(ep << 1) + 1]);
            }
}

// ---------------------------------------------------------------------------
extern "C" void kernel_launch(void* const* d_in, const int* in_sizes, int n_in,
                              void* d_out, int out_size) {
    const float* query = (const float*)d_in[0];
    const int*   mask  = (const int*)d_in[1];   // numpy bool widened to int32
    const float* w_in  = (const float*)d_in[2];
    const float* b_in  = (const float*)d_in[3];
    const float* w_out = (const float*)d_in[4];
    const float* b_out = (const float*)d_in[5];

    float* outAttn = (float*)d_out;                                   // [T,B,E]
    float* outAvg  = (float*)d_out + (size_t)MROWS * EMBED;           // [B,T,S]

    // One-time resource init (streams/events are resources, not work state;
    // the launched work is identical and deterministic on every call).
    static cudaStream_t s_avg = nullptr;
    static cudaEvent_t ev_fork = nullptr, ev_join = nullptr;
    if (s_avg == nullptr) {
        cudaStreamCreateWithFlags(&s_avg, cudaStreamNonBlocking);
        cudaEventCreateWithFlags(&ev_fork, cudaEventDisableTiming);
        cudaEventCreateWithFlags(&ev_join, cudaEventDisableTiming);
    }

    const int gemm_smem = GEMM_SMEM_WORDS * 4;   // 73,728 B
    const int pv_smem   = PV_SMEM_WORDS * 4;     // 55,296 B
    cudaFuncSetAttribute(k_gemm_tf32<0>, cudaFuncAttributeMaxDynamicSharedMemorySize, gemm_smem);
    cudaFuncSetAttribute(k_gemm_tf32<1>, cudaFuncAttributeMaxDynamicSharedMemorySize, gemm_smem);
    cudaFuncSetAttribute(k_pv_mma,       cudaFuncAttributeMaxDynamicSharedMemorySize, pv_smem);

    k_gemm_tf32<0><<<dim3(24, 32), 256, gemm_smem>>>(query, w_in, b_in, nullptr, EMBED);
    k_scores_mma<<<dim3(8, 8, 64), 256>>>();
    k_softmax  <<<dim3(1024, 64), 256>>>(mask);

    // Fork: avg depends only on softmax; run it concurrently with pv+oproj.
    cudaEventRecord(ev_fork, 0);
    cudaStreamWaitEvent(s_avg, ev_fork, 0);
    k_avg<<<16384, 256, 0, s_avg>>>(outAvg);
    cudaEventRecord(ev_join, s_avg);

    k_pv_mma   <<<dim3(8, 64), 256, pv_smem>>>();
    k_gemm_tf32<1><<<dim3(8, 32), 256, gemm_smem>>>(nullptr, w_out, b_out, outAttn, EMBED);

    // Join side stream back into the capture stream.
    cudaStreamWaitEvent(0, ev_join, 0);
}

// round 8
// speedup vs baseline: 3.0620x; 1.0677x over previous
#include <cuda_runtime.h>
#include <math.h>
#include <stdint.h>

#define TLEN   1024
#define BATCH  4
#define EMBED  1024
#define NH     16
#define HD     64
#define QSCALE 0.125f
#define MROWS  (TLEN * BATCH)   // 4096

// Scratch (static device globals — no cudaMalloc anywhere)
__device__ float g_Q[BATCH * NH * TLEN * HD];                 // [b,h,t,d], pre-scaled
__device__ float g_K[BATCH * NH * TLEN * HD];
__device__ float g_V[BATCH * NH * TLEN * HD];
__device__ float g_P[(size_t)BATCH * NH * TLEN * TLEN];       // unnormalized exp tiles
__device__ float g_C[BATCH * NH * TLEN * 16];                 // per-(row,tile) corrections
__device__ float g_A[MROWS * EMBED];                          // attention context [t,b,e]

__device__ __forceinline__ uint32_t f2tf(float f) {
    uint32_t u;
    asm("cvt.rna.tf32.f32 %0, %1;" : "=r"(u) : "f"(f));
    return u;
}

__device__ __forceinline__ void mma_tf32(float* d, const uint32_t* a, const uint32_t* b) {
    asm volatile(
        "mma.sync.aligned.m16n8k8.row.col.f32.tf32.tf32.f32 "
        "{%0,%1,%2,%3}, {%4,%5,%6,%7}, {%8,%9}, {%0,%1,%2,%3};"
        : "+f"(d[0]), "+f"(d[1]), "+f"(d[2]), "+f"(d[3])
        : "r"(a[0]), "r"(a[1]), "r"(a[2]), "r"(a[3]), "r"(b[0]), "r"(b[1]));
}

// ---------------------------------------------------------------------------
// TF32 tensor-core GEMM: C[M,N] = A[M,K] @ B[N,K]^T + bias (from R7, proven)
// ---------------------------------------------------------------------------
#define GEMM_SMEM_WORDS (4 * 128 * 36)
#define AS(buf, r, c) As[(buf) * 4608 + (r) * 36 + (c)]
#define BS(buf, r, c) Bs[(buf) * 4608 + (r) * 36 + (c)]

template <int EPI>
__global__ __launch_bounds__(256) void k_gemm_tf32(const float* __restrict__ Ain,
                                                   const float* __restrict__ B,
                                                   const float* __restrict__ bias,
                                                   float* __restrict__ C,
                                                   int K) {
    const float* A = (EPI == 0) ? Ain : (const float*)g_A;
    extern __shared__ uint32_t smraw[];
    uint32_t* As = smraw;
    uint32_t* Bs = smraw + 2 * 4608;
    const int tid  = threadIdx.x;
    const int lane = tid & 31;
    const int wid  = tid >> 5;
    const int wm   = (wid & 1) << 6;
    const int wn   = (wid >> 1) << 5;
    const int m0   = blockIdx.y << 7;
    const int n0   = blockIdx.x << 7;
    const int ldr = tid >> 3;
    const int ldc = (tid & 7) << 2;
    const int g4 = lane >> 2;
    const int g1 = lane & 3;

    float acc[4][4][4] = {};
    float4 av[4], bv[4];

    const float* Abase = A + (size_t)(m0 + ldr) * K + ldc;
    const float* Bbase = B + (size_t)(n0 + ldr) * K + ldc;

    #pragma unroll
    for (int r = 0; r < 4; r++) {
        av[r] = *(const float4*)(Abase + (size_t)(r << 5) * K);
        bv[r] = *(const float4*)(Bbase + (size_t)(r << 5) * K);
    }
    #pragma unroll
    for (int r = 0; r < 4; r++) {
        uint32_t* pa = &AS(0, (r << 5) + ldr, ldc);
        uint32_t* pb = &BS(0, (r << 5) + ldr, ldc);
        pa[0] = f2tf(av[r].x); pa[1] = f2tf(av[r].y); pa[2] = f2tf(av[r].z); pa[3] = f2tf(av[r].w);
        pb[0] = f2tf(bv[r].x); pb[1] = f2tf(bv[r].y); pb[2] = f2tf(bv[r].z); pb[3] = f2tf(bv[r].w);
    }
    __syncthreads();

    int cur = 0;
    for (int k0 = 0; k0 < K; k0 += 32) {
        const bool has_next = (k0 + 32 < K);
        if (has_next) {
            #pragma unroll
            for (int r = 0; r < 4; r++) {
                av[r] = *(const float4*)(Abase + (size_t)(r << 5) * K + k0 + 32);
                bv[r] = *(const float4*)(Bbase + (size_t)(r << 5) * K + k0 + 32);
            }
        }
        #pragma unroll
        for (int kk = 0; kk < 32; kk += 8) {
            uint32_t a[4][4], b[4][2];
            #pragma unroll
            for (int im = 0; im < 4; im++) {
                int mr = wm + (im << 4) + g4;
                a[im][0] = AS(cur, mr    , kk + g1    );
                a[im][1] = AS(cur, mr + 8, kk + g1    );
                a[im][2] = AS(cur, mr    , kk + g1 + 4);
                a[im][3] = AS(cur, mr + 8, kk + g1 + 4);
            }
            #pragma unroll
            for (int jn = 0; jn < 4; jn++) {
                int nr = wn + (jn << 3) + g4;
                b[jn][0] = BS(cur, nr, kk + g1    );
                b[jn][1] = BS(cur, nr, kk + g1 + 4);
            }
            #pragma unroll
            for (int im = 0; im < 4; im++)
                #pragma unroll
                for (int jn = 0; jn < 4; jn++)
                    mma_tf32(acc[im][jn], a[im], b[jn]);
        }
        if (has_next) {
            int nxt = cur ^ 1;
            #pragma unroll
            for (int r = 0; r < 4; r++) {
                uint32_t* pa = &AS(nxt, (r << 5) + ldr, ldc);
                uint32_t* pb = &BS(nxt, (r << 5) + ldr, ldc);
                pa[0] = f2tf(av[r].x); pa[1] = f2tf(av[r].y); pa[2] = f2tf(av[r].z); pa[3] = f2tf(av[r].w);
                pb[0] = f2tf(bv[r].x); pb[1] = f2tf(bv[r].y); pb[2] = f2tf(bv[r].z); pb[3] = f2tf(bv[r].w);
            }
            __syncthreads();
        }
        cur ^= 1;
    }

    #pragma unroll
    for (int im = 0; im < 4; im++)
        #pragma unroll
        for (int jn = 0; jn < 4; jn++)
            #pragma unroll
            for (int e = 0; e < 4; e++) {
                int m = m0 + wm + (im << 4) + g4 + ((e >> 1) << 3);
                int n = n0 + wn + (jn << 3) + (g1 << 1) + (e & 1);
                float v = acc[im][jn][e] + bias[n];
                if (EPI == 0) {
                    int t = m >> 2, bb = m & 3;
                    int c = n >> 10;
                    int ee = n & 1023;
                    int h = ee >> 6, d = ee & 63;
                    int idx = (((bb << 4) + h) * TLEN + t) * HD + d;
                    if (c == 0)      g_Q[idx] = v * QSCALE;
                    else if (c == 1) g_K[idx] = v;
                    else             g_V[idx] = v;
                } else {
                    C[(size_t)m * EMBED + n] = v;
                }
            }
}

// ---------------------------------------------------------------------------
// Fused flash attention per (bh, 128 t-rows): S=QK^T (tf32 MMA), online
// softmax (causal + padding), P~=exp(S-m_tile) written to g_P, O += P~·V
// (tf32 MMA) with rescaling. Correction factors to g_C for the avg kernel.
// s-tiles of 64. 8 warps: 2 m-rows x 4 n-cols, warp tile 64x16.
// ---------------------------------------------------------------------------
#define ATT_OFF_Q   0            // 128x68 words
#define ATT_OFF_K   8704         // 64x68
#define ATT_OFF_V   13056        // 64x68 (transposed: [d][s])
#define ATT_OFF_P   17408        // 128x68
#define ATT_OFF_RED 26112        // redm[4][128] + reds[4][128]
#define ATT_OFF_MT  27136        // m_tile[128][16]
#define ATT_OFF_PAD 29184        // 64 ints
#define ATT_SMEM_WORDS 29248

__global__ __launch_bounds__(256) void k_attn(const int* __restrict__ pad) {
    extern __shared__ uint32_t sm[];
    uint32_t* Qs = sm + ATT_OFF_Q;
    uint32_t* Ks = sm + ATT_OFF_K;
    uint32_t* Vs = sm + ATT_OFF_V;
    uint32_t* Ps = sm + ATT_OFF_P;
    float* redm = (float*)(sm + ATT_OFF_RED);
    float* reds = redm + 512;
    float* mtl  = (float*)(sm + ATT_OFF_MT);
    int*   pads = (int*)(sm + ATT_OFF_PAD);

    const int bh = blockIdx.y;
    const int t0 = (7 - blockIdx.x) << 7;      // big tiles first
    const int b  = bh >> 4;
    const int h  = bh & 15;
    const int tid  = threadIdx.x;
    const int lane = tid & 31;
    const int wid  = tid >> 5;
    const int wm = (wid & 1) << 6;
    const int wn = (wid >> 1) << 4;            // 0/16/32/48
    const int g4 = lane >> 2;
    const int g1 = lane & 3;
    const int wc = wid >> 1;

    const float* Qg = g_Q + (size_t)bh * TLEN * HD;
    const float* Kg = g_K + (size_t)bh * TLEN * HD;
    const float* Vg = g_V + (size_t)bh * TLEN * HD;
    float* Pg = g_P + (size_t)bh * TLEN * TLEN;

    // Q tile 128x64 -> smem (tf32)
    {
        int qr = tid >> 1;
        int qc = (tid & 1) << 5;
        #pragma unroll
        for (int j = 0; j < 8; j++) {
            float4 q = *(const float4*)(Qg + (size_t)(t0 + qr) * HD + qc + j * 4);
            uint32_t* p = &Qs[qr * 68 + qc + j * 4];
            p[0] = f2tf(q.x); p[1] = f2tf(q.y); p[2] = f2tf(q.z); p[3] = f2tf(q.w);
        }
    }

    float m_run[4][2], l_run[4][2];
    float acc_o[4][2][4] = {};
    #pragma unroll
    for (int im = 0; im < 4; im++) {
        m_run[im][0] = m_run[im][1] = -1e30f;
        l_run[im][0] = l_run[im][1] = 0.f;
    }
    __syncthreads();

    const int nt = (t0 + 128) >> 6;   // 2..16 tiles of 64
    const int kr = tid >> 2;
    const int kc = (tid & 3) << 4;

    for (int it = 0; it < nt; it++) {
        const int s0 = it << 6;
        float4 kf[4], vf[4];
        #pragma unroll
        for (int j = 0; j < 4; j++) {
            kf[j] = *(const float4*)(Kg + (size_t)(s0 + kr) * HD + kc + j * 4);
            vf[j] = *(const float4*)(Vg + (size_t)(s0 + kr) * HD + kc + j * 4);
        }
        int padv = (tid < 64) ? pad[b * TLEN + s0 + tid] : 0;
        __syncthreads();                       // prev tile's smem consumed
        #pragma unroll
        for (int j = 0; j < 4; j++) {
            uint32_t* p = &Ks[kr * 68 + kc + j * 4];
            p[0] = f2tf(kf[j].x); p[1] = f2tf(kf[j].y); p[2] = f2tf(kf[j].z); p[3] = f2tf(kf[j].w);
            Vs[(kc + j * 4 + 0) * 68 + kr] = f2tf(vf[j].x);
            Vs[(kc + j * 4 + 1) * 68 + kr] = f2tf(vf[j].y);
            Vs[(kc + j * 4 + 2) * 68 + kr] = f2tf(vf[j].z);
            Vs[(kc + j * 4 + 3) * 68 + kr] = f2tf(vf[j].w);
        }
        if (tid < 64) pads[tid] = padv;
        __syncthreads();

        // ---- S = Q K^T  (128x64, K=64) ----
        float accs[4][2][4] = {};
        #pragma unroll
        for (int kk = 0; kk < 64; kk += 8) {
            uint32_t a[4][4], bf[2][2];
            #pragma unroll
            for (int im = 0; im < 4; im++) {
                int mr = wm + (im << 4) + g4;
                a[im][0] = Qs[mr * 68 + kk + g1];
                a[im][1] = Qs[(mr + 8) * 68 + kk + g1];
                a[im][2] = Qs[mr * 68 + kk + g1 + 4];
                a[im][3] = Qs[(mr + 8) * 68 + kk + g1 + 4];
            }
            #pragma unroll
            for (int jn = 0; jn < 2; jn++) {
                int nr = wn + (jn << 3) + g4;
                bf[jn][0] = Ks[nr * 68 + kk + g1];
                bf[jn][1] = Ks[nr * 68 + kk + g1 + 4];
            }
            #pragma unroll
            for (int im = 0; im < 4; im++)
                #pragma unroll
                for (int jn = 0; jn < 2; jn++)
                    mma_tf32(accs[im][jn], a[im], bf[jn]);
        }

        // ---- mask + tile row max ----
        float mloc[4][2];
        #pragma unroll
        for (int im = 0; im < 4; im++)
            #pragma unroll
            for (int ep = 0; ep < 2; ep++) {
                int t = t0 + wm + (im << 4) + g4 + (ep << 3);
                float mm = -1e30f;
                #pragma unroll
                for (int jn = 0; jn < 2; jn++)
                    #pragma unroll
                    for (int c = 0; c < 2; c++) {
                        int s = s0 + wn + (jn << 3) + (g1 << 1) + c;
                        bool ok = (s <= t) && (pads[s - s0] == 0);
                        float v = ok ? accs[im][jn][(ep << 1) + c] : -1e30f;
                        accs[im][jn][(ep << 1) + c] = v;
                        mm = fmaxf(mm, v);
                    }
                mm = fmaxf(mm, __shfl_xor_sync(0xffffffffu, mm, 1));
                mm = fmaxf(mm, __shfl_xor_sync(0xffffffffu, mm, 2));
                mloc[im][ep] = mm;
            }
        if (g1 == 0) {
            #pragma unroll
            for (int im = 0; im < 4; im++)
                #pragma unroll
                for (int ep = 0; ep < 2; ep++)
                    redm[wc * 128 + wm + (im << 4) + g4 + (ep << 3)] = mloc[im][ep];
        }
        __syncthreads();

        // ---- combine max, rescale ----
        float m_new[4][2];
        #pragma unroll
        for (int im = 0; im < 4; im++)
            #pragma unroll
            for (int ep = 0; ep < 2; ep++) {
                int row = wm + (im << 4) + g4 + (ep << 3);
                float mt = fmaxf(fmaxf(redm[row], redm[128 + row]),
                                 fmaxf(redm[256 + row], redm[384 + row]));
                float mn = fmaxf(m_run[im][ep], mt);
                float f = __expf(m_run[im][ep] - mn);
                m_new[im][ep] = mn;
                m_run[im][ep] = mn;
                l_run[im][ep] *= f;
                #pragma unroll
                for (int jn = 0; jn < 2; jn++) {
                    acc_o[im][jn][(ep << 1) + 0] *= f;
                    acc_o[im][jn][(ep << 1) + 1] *= f;
                }
                if (wc == 0 && g1 == 0) mtl[row * 16 + it] = mn;
            }

        // ---- p = exp, write gmem + smem, row sums ----
        #pragma unroll
        for (int im = 0; im < 4; im++)
            #pragma unroll
            for (int ep = 0; ep < 2; ep++) {
                int t = t0 + wm + (im << 4) + g4 + (ep << 3);
                int rowL = t - t0;
                float ssum = 0.f;
                #pragma unroll
                for (int jn = 0; jn < 2; jn++) {
                    int cb = wn + (jn << 3) + (g1 << 1);
                    float p0 = __expf(accs[im][jn][(ep << 1) + 0] - m_new[im][ep]);
                    float p1 = __expf(accs[im][jn][(ep << 1) + 1] - m_new[im][ep]);
                    ssum += p0 + p1;
                    *(float2*)(Pg + (size_t)t * TLEN + s0 + cb) = make_float2(p0, p1);
                    Ps[rowL * 68 + cb]     = f2tf(p0);
                    Ps[rowL * 68 + cb + 1] = f2tf(p1);
                }
                ssum += __shfl_xor_sync(0xffffffffu, ssum, 1);
                ssum += __shfl_xor_sync(0xffffffffu, ssum, 2);
                if (g1 == 0) reds[wc * 128 + rowL] = ssum;
            }
        __syncthreads();
        #pragma unroll
        for (int im = 0; im < 4; im++)
            #pragma unroll
            for (int ep = 0; ep < 2; ep++) {
                int row = wm + (im << 4) + g4 + (ep << 3);
                l_run[im][ep] += reds[row] + reds[128 + row] + reds[256 + row] + reds[384 + row];
            }

        // ---- O += P~ V  (128x64, K=64) ----
        #pragma unroll
        for (int kk = 0; kk < 64; kk += 8) {
            uint32_t a[4][4], bf[2][2];
            #pragma unroll
            for (int im = 0; im < 4; im++) {
                int mr = wm + (im << 4) + g4;
                a[im][0] = Ps[mr * 68 + kk + g1];
                a[im][1] = Ps[(mr + 8) * 68 + kk + g1];
                a[im][2] = Ps[mr * 68 + kk + g1 + 4];
                a[im][3] = Ps[(mr + 8) * 68 + kk + g1 + 4];
            }
            #pragma unroll
            for (int jn = 0; jn < 2; jn++) {
                int nr = wn + (jn << 3) + g4;
                bf[jn][0] = Vs[nr * 68 + kk + g1];
                bf[jn][1] = Vs[nr * 68 + kk + g1 + 4];
            }
            #pragma unroll
            for (int im = 0; im < 4; im++)
                #pragma unroll
                for (int jn = 0; jn < 2; jn++)
                    mma_tf32(acc_o[im][jn], a[im], bf[jn]);
        }
    }

    // ---- epilogue: O/l -> g_A; corrections -> g_C ----
    #pragma unroll
    for (int im = 0; im < 4; im++)
        #pragma unroll
        for (int ep = 0; ep < 2; ep++) {
            int t = t0 + wm + (im << 4) + g4 + (ep << 3);
            float inv = 1.f / l_run[im][ep];
            #pragma unroll
            for (int jn = 0; jn < 2; jn++) {
                int d = wn + (jn << 3) + (g1 << 1);
                float* o = g_A + ((size_t)t * BATCH + b) * EMBED + (h << 6) + d;
                *(float2*)o = make_float2(acc_o[im][jn][(ep << 1) + 0] * inv,
                                          acc_o[im][jn][(ep << 1) + 1] * inv);
            }
        }
    if (wc == 0 && g1 == 0) {
        #pragma unroll
        for (int im = 0; im < 4; im++)
            #pragma unroll
            for (int ep = 0; ep < 2; ep++) {
                int row = wm + (im << 4) + g4 + (ep << 3);
                int t = t0 + row;
                float inv = 1.f / l_run[im][ep];
                float mfin = m_run[im][ep];
                for (int it2 = 0; it2 < nt; it2++) {
                    float c = __expf(mtl[row * 16 + it2] - mfin) * inv;
                    g_C[((size_t)bh * TLEN + t) * 16 + it2] = c;
                }
            }
    }
}

// ---------------------------------------------------------------------------
// avg_weights[b,t,s] = (1/16) sum_h P~[bh,t,s] * C[bh,t,s>>6]; 0 for s>t.
// ---------------------------------------------------------------------------
__global__ __launch_bounds__(256) void k_avg(float* __restrict__ outAvg) {
    const int idx = blockIdx.x * 256 + threadIdx.x;
    const int s = idx & 1023;
    const int t = (idx >> 10) & 1023;
    const int b = idx >> 20;
    if (s > t) { outAvg[idx] = 0.f; return; }
    const int tile = s >> 6;
    float sum = 0.f;
    #pragma unroll
    for (int h = 0; h < 16; h++) {
        size_t base = (size_t)((b << 4) + h) * TLEN + t;
        sum += g_P[base * TLEN + s] * g_C[base * 16 + tile];
    }
    outAvg[idx] = sum * 0.0625f;
}

// ---------------------------------------------------------------------------
extern "C" void kernel_launch(void* const* d_in, const int* in_sizes, int n_in,
                              void* d_out, int out_size) {
    const float* query = (const float*)d_in[0];
    const int*   mask  = (const int*)d_in[1];   // numpy bool widened to int32
    const float* w_in  = (const float*)d_in[2];
    const float* b_in  = (const float*)d_in[3];
    const float* w_out = (const float*)d_in[4];
    const float* b_out = (const float*)d_in[5];

    float* outAttn = (float*)d_out;                                   // [T,B,E]
    float* outAvg  = (float*)d_out + (size_t)MROWS * EMBED;           // [B,T,S]

    static cudaStream_t s_avg = nullptr;
    static cudaEvent_t ev_fork = nullptr, ev_join = nullptr;
    if (s_avg == nullptr) {
        cudaStreamCreateWithFlags(&s_avg, cudaStreamNonBlocking);
        cudaEventCreateWithFlags(&ev_fork, cudaEventDisableTiming);
        cudaEventCreateWithFlags(&ev_join, cudaEventDisableTiming);
    }

    const int gemm_smem = GEMM_SMEM_WORDS * 4;   // 73,728 B
    const int attn_smem = ATT_SMEM_WORDS * 4;    // 116,992 B
    cudaFuncSetAttribute(k_gemm_tf32<0>, cudaFuncAttributeMaxDynamicSharedMemorySize, gemm_smem);
    cudaFuncSetAttribute(k_gemm_tf32<1>, cudaFuncAttributeMaxDynamicSharedMemorySize, gemm_smem);
    cudaFuncSetAttribute(k_attn,         cudaFuncAttributeMaxDynamicSharedMemorySize, attn_smem);

    k_gemm_tf32<0><<<dim3(24, 32), 256, gemm_smem>>>(query, w_in, b_in, nullptr, EMBED);
    k_attn<<<dim3(8, 64), 256, attn_smem>>>(mask);

    // Fork: avg depends only on k_attn; run concurrently with out-proj.
    cudaEventRecord(ev_fork, 0);
    cudaStreamWaitEvent(s_avg, ev_fork, 0);
    k_avg<<<16384, 256, 0, s_avg>>>(outAvg);
    cudaEventRecord(ev_join, s_avg);

    k_gemm_tf32<1><<<dim3(8, 32), 256, gemm_smem>>>(nullptr, w_out, b_out, outAttn, EMBED);

    cudaStreamWaitEvent(0, ev_join, 0);
}